// round 9
// baseline (speedup 1.0000x reference)
#include <cuda_runtime.h>
#include <math.h>
#include <stdint.h>

// Problem constants
constexpr int Lc    = 50;
constexpr int NSEQ  = 32 * 40;     // 1280 sequences
constexpr int NR    = NSEQ * Lc;   // 64000 (seq,time) rows
constexpr int H     = 128;
constexpr int G4    = 512;         // 4*H gates

// ---------------------------------------------------------------------------
// Device scratch
// ---------------------------------------------------------------------------
__device__ float g_X0[(size_t)NR * 64];
__device__ float g_Xa[(size_t)NR * 256];
__device__ float g_Xb[(size_t)NR * 256];
__device__ float g_xg[2][(size_t)NR * G4];   // t-major: [dir][t][seq][512]
__device__ float g_hbuf[2][2][NSEQ * H];     // [step parity][dir][row*H+col]
__device__ int   g_flags[2][2][32][10];      // [dir][jtile][rowgroup][rg]
__device__ float g_agg[(size_t)NSEQ * 768];
__device__ float g_t1[(size_t)NSEQ * 512];
__device__ float g_t2[(size_t)NSEQ * 512];
// pre-converted tf32 weights: wih0 | wih1 | wih2 | wout1 | wout2
__device__ uint32_t g_Wtf[65536 + 262144 + 262144 + 393216 + 131072];

// ---------------------------------------------------------------------------
// helpers
// ---------------------------------------------------------------------------
__device__ __forceinline__ float2 ffma2(float2 a, float2 b, float2 c) {
    unsigned long long ud;
    asm("fma.rn.f32x2 %0, %1, %2, %3;"
        : "=l"(ud)
        : "l"(*(unsigned long long*)&a),
          "l"(*(unsigned long long*)&b),
          "l"(*(unsigned long long*)&c));
    float2 d; *(unsigned long long*)&d = ud; return d;
}
__device__ __forceinline__ float2 pack2(float lo, float hi) {
    float2 r; r.x = lo; r.y = hi; return r;
}
__device__ __forceinline__ float sigm_(float x) {
    return __fdividef(1.0f, 1.0f + __expf(-x));
}
__device__ __forceinline__ float tanh_(float x) {
    return __fdividef(2.0f, 1.0f + __expf(-2.0f * x)) - 1.0f;
}
__device__ __forceinline__ uint32_t f2tf(float x) {
    uint32_t r;
    asm("cvt.rna.tf32.f32 %0, %1;" : "=r"(r) : "f"(x));
    return r;
}
__device__ __forceinline__ uint32_t cvsel(float x, int pre) {
    return pre ? __float_as_uint(x) : f2tf(x);
}
__device__ __forceinline__ void mma_tf32(float* d, const uint32_t* a,
                                         const uint32_t* b) {
    asm volatile(
        "mma.sync.aligned.m16n8k8.row.col.f32.tf32.tf32.f32 "
        "{%0,%1,%2,%3}, {%4,%5,%6,%7}, {%8,%9}, {%0,%1,%2,%3};\n"
        : "+f"(d[0]), "+f"(d[1]), "+f"(d[2]), "+f"(d[3])
        : "r"(a[0]), "r"(a[1]), "r"(a[2]), "r"(a[3]), "r"(b[0]), "r"(b[1]));
}

// ---------------------------------------------------------------------------
// reset pairwise-sync flags (once per replay): 2*2*32*10 = 1280 ints
// ---------------------------------------------------------------------------
__global__ void reset_flags() {
    int i = blockIdx.x * 256 + threadIdx.x;
    if (i < 1280) ((int*)g_flags)[i] = 0;
}

// ---------------------------------------------------------------------------
// weight -> tf32 pre-conversion
// ---------------------------------------------------------------------------
__global__ __launch_bounds__(256) void conv_tf32(
    const float* __restrict__ src, uint32_t* __restrict__ dst, int n)
{
    int i = blockIdx.x * 256 + threadIdx.x;
    if (i < n) dst[i] = f2tf(src[i]);
}

// ---------------------------------------------------------------------------
// Kernel 1: input projection (output pre-rounded to tf32 — feeds GEMM only)
// ---------------------------------------------------------------------------
__global__ __launch_bounds__(256) void inproj_kernel(
    const float* __restrict__ imu, const float* __restrict__ Win,
    const float* __restrict__ bin)
{
    int idx = blockIdx.x * 256 + threadIdx.x;
    int row = idx >> 6;
    int jj  = idx & 63;
    int l   = row % Lc;
    const float* xr = imu + (size_t)row * 6;
    float t    = (float)l * (1.0f / 49.0f);
    float rate = 1.0f;
    float acc = bin[jj];
#pragma unroll
    for (int k = 0; k < 6; k++) acc = fmaf(xr[k], Win[k * 64 + jj], acc);
    acc = fmaf(t,    Win[6 * 64 + jj], acc);
    acc = fmaf(rate, Win[7 * 64 + jj], acc);
    g_X0[(size_t)row * 64 + jj] = __uint_as_float(f2tf(fmaxf(acc, 0.0f)));
}

// ---------------------------------------------------------------------------
// Kernel 2: tf32 tensor-core GEMM + bias. permute: t-major output rows.
// atf/btf: A/B already tf32-rounded (skip cvt).
// ---------------------------------------------------------------------------
constexpr int APITCH = 132;
constexpr int BPITCH = 260;
constexpr int ASZ = 4 * 8 * APITCH;
constexpr int BSZ = 4 * 4 * BPITCH;
constexpr int GEMM_SMEM = (2 * ASZ + 2 * BSZ) * 4;

__device__ __forceinline__ int asI(int buf, int ks, int c, int q) {
    return ((buf * 4 + ks) * 8 + c) * APITCH + q;
}
__device__ __forceinline__ int bsI(int buf, int ks, int kp, int q) {
    return ((buf * 4 + ks) * 4 + kp) * BPITCH + q;
}

__global__ __launch_bounds__(256) void tf32_gemm(
    const float* __restrict__ A, const float* __restrict__ B,
    float* __restrict__ C,
    const float* __restrict__ bias1, const float* __restrict__ bias2,
    int M, int N, int K,
    long long sB, long long sC, long long sBias, int nbx, int permute,
    int atf, int btf)
{
    extern __shared__ uint32_t sm[];
    uint32_t* As = sm;
    uint32_t* Bs = sm + 2 * ASZ;

    const int dir = blockIdx.x / nbx;
    const int nb  = blockIdx.x % nbx;
    const int mb  = blockIdx.y;
    B += (size_t)dir * sB;
    C += (size_t)dir * sC;
    const float* b1 = bias1 + (size_t)dir * sBias;
    const float* b2 = bias2 ? bias2 + (size_t)dir * sBias : nullptr;
    const bool hasB2 = (b2 != nullptr);

    const int tid  = threadIdx.x;
    const int warp = tid >> 5, lane = tid & 31;
    const int wR = warp >> 2, wC = warp & 3;
    const int g  = lane >> 2, tig = lane & 3;

    const float* Ab = A + (size_t)(mb * 128) * K;
    const float* Bb = B + nb * 128;

    const int lr  = tid >> 3;
    const int lc4 = (tid & 7) * 4;
    const int aks = lc4 >> 3, ac0 = lc4 & 7;
    const int bks = lr >> 3, br8 = lr & 7;
    const int bkp = br8 & 3, bhalf = br8 >> 2;

    float acc[4][4][4];
#pragma unroll
    for (int mt = 0; mt < 4; mt++)
#pragma unroll
        for (int nt = 0; nt < 4; nt++)
#pragma unroll
            for (int q = 0; q < 4; q++) acc[mt][nt][q] = 0.0f;

    const int niter = K / 32;

    {
#pragma unroll
        for (int i = 0; i < 4; i++) {
            int r = lr + i * 32;
            float4 v = *(const float4*)(Ab + (size_t)r * K + lc4);
            int q = ((r >> 4) << 4) + ((r & 7) << 1) + ((r >> 3) & 1);
            uint32_t* d = &As[asI(0, aks, ac0, q)];
            d[0] = cvsel(v.x, atf); d[APITCH] = cvsel(v.y, atf);
            d[2 * APITCH] = cvsel(v.z, atf); d[3 * APITCH] = cvsel(v.w, atf);
        }
#pragma unroll
        for (int i = 0; i < 4; i++) {
            int col = lc4 + i * 32;
            float4 v = *(const float4*)(Bb + (size_t)lr * N + col);
            uint32_t* d = &Bs[bsI(0, bks, bkp, col * 2 + bhalf)];
            d[0] = cvsel(v.x, btf); d[2] = cvsel(v.y, btf);
            d[4] = cvsel(v.z, btf); d[6] = cvsel(v.w, btf);
        }
    }
    __syncthreads();

    for (int it = 0; it < niter; it++) {
        const int cur = it & 1, nxt = cur ^ 1;
        const bool more = (it + 1 < niter);
        float4 av[4], bv[4];
        if (more) {
            int k0 = (it + 1) * 32;
#pragma unroll
            for (int i = 0; i < 4; i++) {
                av[i] = *(const float4*)(Ab + (size_t)(lr + i * 32) * K + k0 + lc4);
                bv[i] = *(const float4*)(Bb + (size_t)(k0 + lr) * N + lc4 + i * 32);
            }
        }

#pragma unroll
        for (int ks = 0; ks < 4; ks++) {
            uint32_t af[4][4];
#pragma unroll
            for (int mt = 0; mt < 4; mt++) {
                int q = ((wR * 4 + mt) << 4) + (g << 1);
                uint2 u0 = *(const uint2*)&As[asI(cur, ks, tig, q)];
                uint2 u1 = *(const uint2*)&As[asI(cur, ks, tig + 4, q)];
                af[mt][0] = u0.x; af[mt][1] = u0.y;
                af[mt][2] = u1.x; af[mt][3] = u1.y;
            }
            uint32_t bf[4][2];
#pragma unroll
            for (int nt = 0; nt < 4; nt++) {
                int n = wC * 32 + nt * 8 + g;
                uint2 u = *(const uint2*)&Bs[bsI(cur, ks, tig, n * 2)];
                bf[nt][0] = u.x; bf[nt][1] = u.y;
            }
#pragma unroll
            for (int mt = 0; mt < 4; mt++)
#pragma unroll
                for (int nt = 0; nt < 4; nt++)
                    mma_tf32(acc[mt][nt], af[mt], bf[nt]);
        }

        if (more) {
#pragma unroll
            for (int i = 0; i < 4; i++) {
                int r = lr + i * 32;
                int q = ((r >> 4) << 4) + ((r & 7) << 1) + ((r >> 3) & 1);
                uint32_t* d = &As[asI(nxt, aks, ac0, q)];
                d[0] = cvsel(av[i].x, atf); d[APITCH] = cvsel(av[i].y, atf);
                d[2 * APITCH] = cvsel(av[i].z, atf); d[3 * APITCH] = cvsel(av[i].w, atf);
                int col = lc4 + i * 32;
                uint32_t* db = &Bs[bsI(nxt, bks, bkp, col * 2 + bhalf)];
                db[0] = cvsel(bv[i].x, btf); db[2] = cvsel(bv[i].y, btf);
                db[4] = cvsel(bv[i].z, btf); db[6] = cvsel(bv[i].w, btf);
            }
        }
        __syncthreads();
    }

#pragma unroll
    for (int mt = 0; mt < 4; mt++) {
        int rowa = mb * 128 + wR * 64 + mt * 16 + g;
        int rowb = rowa + 8;
        size_t ra = permute ? ((size_t)(rowa % Lc) * NSEQ + rowa / Lc) : (size_t)rowa;
        size_t rb = permute ? ((size_t)(rowb % Lc) * NSEQ + rowb / Lc) : (size_t)rowb;
#pragma unroll
        for (int nt = 0; nt < 4; nt++) {
            int colg = nb * 128 + wC * 32 + nt * 8 + 2 * tig;
            float bx = b1[colg], by = b1[colg + 1];
            if (hasB2) { bx += b2[colg]; by += b2[colg + 1]; }
            float2 v0 = pack2(acc[mt][nt][0] + bx, acc[mt][nt][1] + by);
            float2 v1 = pack2(acc[mt][nt][2] + bx, acc[mt][nt][3] + by);
            *(float2*)(C + ra * N + colg) = v0;
            *(float2*)(C + rb * N + colg) = v1;
        }
    }
}

// ---------------------------------------------------------------------------
// Kernel 3: PERSISTENT BiLSTM layer, warp-pair decoupled, 4 rows/thread.
// 128 CTAs x 640 threads. CTA = (dir, jt, rowgroup of 40 rows).
// rg = tid>>6 (0..9) owns 4 rows; jcol = tid&63 is the hidden col within jt.
// Sync: named barrier per rg (64 threads) + per-rg release/acquire flags.
// k-loop register-prefetches k+1 (wrap &127 stays in-bounds).
// roundout: store Xout pre-rounded to tf32 (layers whose output feeds GEMM only)
// ---------------------------------------------------------------------------
#define BARRG(rgid) asm volatile("bar.sync %0, 64;" :: "r"(rgid) : "memory")

__global__ __launch_bounds__(640) void lstm_layer(
    const float* __restrict__ Whh,
    const float* __restrict__ xgb,   // t-major [dir][t][seq][512]
    float* __restrict__ Xout,
    int layer, int roundout)
{
    extern __shared__ float smem[];
    float4* ws  = (float4*)smem;                 // [128][64] gate quads
    float*  hsf = smem + 128 * 64 * 4;
    constexpr int RGSZ = 2 * 128 * 2;            // floats per rg slice
    constexpr int HBUF = 10 * RGSZ;              // floats per buffer

    const int bx   = blockIdx.x;
    const int dir  = bx >> 6;
    const int jt   = (bx >> 5) & 1;
    const int rgI  = bx & 31;
    const int row0 = rgI * 40;
    const int tid  = threadIdx.x;
    const int jcol = tid & 63;
    const int rg   = tid >> 6;                   // 0..9
    const int col  = (jt << 6) + jcol;
    const int rbase = row0 + rg * 4;
    const int base = layer * Lc;
    const bool leader = (tid & 63) == 0;

    const float* W   = Whh + (size_t)dir * (H * G4);
    const float* xgd = xgb + (size_t)dir * NR * G4;
    int* myflag = &g_flags[dir][jt][rgI][rg];
    int* pflag  = &g_flags[dir][jt ^ 1][rgI][rg];

    for (int idx = tid; idx < 128 * 64; idx += 640) {
        int k = idx >> 6, j = idx & 63;
        const float* wk = W + (size_t)k * G4 + (jt << 6) + j;
        ws[idx] = make_float4(wk[0], wk[128], wk[256], wk[384]);
    }
    __syncthreads();

    float c[4];
#pragma unroll
    for (int r = 0; r < 4; r++) c[r] = 0.0f;

    for (int step = 0; step < Lc; step++) {
        const int tin = dir ? (Lc - 1 - step) : step;

        // xg loads (t-major, contiguous per step)
        float2 acc2[4][2];
        const float* xp = xgd + ((size_t)tin * NSEQ + rbase) * G4 + col;
#pragma unroll
        for (int p = 0; p < 2; p++) {
            const float* xa = xp + (size_t)(2 * p) * G4;
            const float* xb = xa + G4;
#pragma unroll
            for (int gi = 0; gi < 4; gi++)
                acc2[gi][p] = pack2(xa[gi * 128], xb[gi * 128]);
        }

        if (step > 0) {
            if (leader) {
                const int want = base + step;
                int v;
                do {
                    asm volatile("ld.acquire.gpu.global.b32 %0, [%1];"
                                 : "=r"(v) : "l"(pflag) : "memory");
                } while (v < want);
            }
            BARRG(rg);

            // restage partner half (4 rows, this thread's partner col)
            {
                const float* hbg = g_hbuf[(step + 1) & 1][dir];
                float* hc = hsf + ((step + 1) & 1) * HBUF + rg * RGSZ;
                int pc = ((jt ^ 1) << 6) + jcol;
#pragma unroll
                for (int r = 0; r < 4; r++)
                    hc[(((r >> 1) << 7) + pc) * 2 + (r & 1)] =
                        hbg[(size_t)(rbase + r) * H + pc];
            }
            BARRG(rg);

            // k-loop with register prefetch of k+1
            const float2* hrow2 =
                (const float2*)(hsf + ((step + 1) & 1) * HBUF + rg * RGSZ);
            float4 w4 = ws[jcol];
            float2 ha = hrow2[0];
            float2 hb = hrow2[128];
#pragma unroll 8
            for (int k = 0; k < 128; k++) {
                const int kn = (k + 1) & 127;
                float4 w4n = ws[(kn << 6) + jcol];
                float2 han = hrow2[kn];
                float2 hbn = hrow2[128 + kn];
                float2 w0 = pack2(w4.x, w4.x);
                float2 w1 = pack2(w4.y, w4.y);
                float2 w2 = pack2(w4.z, w4.z);
                float2 w3 = pack2(w4.w, w4.w);
                acc2[0][0] = ffma2(ha, w0, acc2[0][0]);
                acc2[1][0] = ffma2(ha, w1, acc2[1][0]);
                acc2[2][0] = ffma2(ha, w2, acc2[2][0]);
                acc2[3][0] = ffma2(ha, w3, acc2[3][0]);
                acc2[0][1] = ffma2(hb, w0, acc2[0][1]);
                acc2[1][1] = ffma2(hb, w1, acc2[1][1]);
                acc2[2][1] = ffma2(hb, w2, acc2[2][1]);
                acc2[3][1] = ffma2(hb, w3, acc2[3][1]);
                w4 = w4n; ha = han; hb = hbn;
            }
        }

        // gates + state update
        float hval[4];
#pragma unroll
        for (int p = 0; p < 2; p++) {
            float i0 = sigm_(acc2[0][p].x), i1 = sigm_(acc2[0][p].y);
            float f0 = sigm_(acc2[1][p].x), f1 = sigm_(acc2[1][p].y);
            float ga = tanh_(acc2[2][p].x), gb = tanh_(acc2[2][p].y);
            float o0 = sigm_(acc2[3][p].x), o1 = sigm_(acc2[3][p].y);
            float c0 = fmaf(f0, c[2 * p],     i0 * ga);
            float c1 = fmaf(f1, c[2 * p + 1], i1 * gb);
            c[2 * p] = c0; c[2 * p + 1] = c1;
            hval[2 * p]     = o0 * tanh_(c0);
            hval[2 * p + 1] = o1 * tanh_(c1);
        }

        // publish own half: local smem + global for partner, then flag
        if (step < Lc - 1) {
            float* hw  = hsf + (step & 1) * HBUF + rg * RGSZ;
            float* hbw = g_hbuf[step & 1][dir];
#pragma unroll
            for (int r = 0; r < 4; r++) {
                hw[(((r >> 1) << 7) + col) * 2 + (r & 1)] = hval[r];
                hbw[(size_t)(rbase + r) * H + col] = hval[r];
            }
            BARRG(rg);
            if (leader) {
                int dummy;
                asm volatile("atom.release.gpu.global.exch.b32 %0, [%1], %2;"
                             : "=r"(dummy) : "l"(myflag), "r"(base + step + 1)
                             : "memory");
            }
        }

        // layer output
#pragma unroll
        for (int r = 0; r < 4; r++) {
            float v = hval[r];
            if (roundout) v = __uint_as_float(f2tf(v));
            Xout[((size_t)(rbase + r) * Lc + tin) * 256 + dir * H + col] = v;
        }
    }
}

// ---------------------------------------------------------------------------
// Kernel 4: aggregation
// ---------------------------------------------------------------------------
__global__ __launch_bounds__(256) void agg_kernel(const float* __restrict__ X)
{
    int n = blockIdx.x, f = threadIdx.x;
    const float* base = X + (size_t)n * Lc * 256 + f;
    float s = 0.0f, m = -1e30f;
#pragma unroll 5
    for (int l = 0; l < Lc; l++) {
        float v = base[(size_t)l * 256];
        s += v; m = fmaxf(m, v);
    }
    g_agg[(size_t)n * 768 + f]       = s * (1.0f / Lc);
    g_agg[(size_t)n * 768 + 256 + f] = m;
    g_agg[(size_t)n * 768 + 512 + f] = (f < H) ? base[(Lc - 1) * 256] : base[0];
}

// ---------------------------------------------------------------------------
// Kernel 5: LayerNorm(512) + ReLU
// ---------------------------------------------------------------------------
__global__ __launch_bounds__(256) void ln_relu(
    const float* __restrict__ x, float* __restrict__ y,
    const float* __restrict__ gam, const float* __restrict__ bet)
{
    int row = blockIdx.x, tid = threadIdx.x;
    const float* xr = x + (size_t)row * 512;
    float v0 = xr[tid], v1 = xr[tid + 256];
    float s = v0 + v1, q = v0 * v0 + v1 * v1;
    __shared__ float ss[8], sq[8];
#pragma unroll
    for (int o = 16; o > 0; o >>= 1) {
        s += __shfl_down_sync(~0u, s, o);
        q += __shfl_down_sync(~0u, q, o);
    }
    int w = tid >> 5;
    if ((tid & 31) == 0) { ss[w] = s; sq[w] = q; }
    __syncthreads();
    if (tid == 0) {
        float S = 0.0f, Q = 0.0f;
        for (int i = 0; i < 8; i++) { S += ss[i]; Q += sq[i]; }
        ss[0] = S; sq[0] = Q;
    }
    __syncthreads();
    float mu  = ss[0] * (1.0f / 512.0f);
    float var = sq[0] * (1.0f / 512.0f) - mu * mu;
    float rs  = rsqrtf(var + 1e-5f);
    y[(size_t)row * 512 + tid]       = fmaxf((v0 - mu) * rs * gam[tid]       + bet[tid],       0.0f);
    y[(size_t)row * 512 + tid + 256] = fmaxf((v1 - mu) * rs * gam[tid + 256] + bet[tid + 256], 0.0f);
}

// ---------------------------------------------------------------------------
// Host orchestration
// ---------------------------------------------------------------------------
extern "C" void kernel_launch(void* const* d_in, const int* in_sizes, int n_in,
                              void* d_out, int out_size)
{
    const float* imu   = (const float*)d_in[0];
    const float* W_in  = (const float*)d_in[1];
    const float* b_in  = (const float*)d_in[2];
    const float* Wih[3] = {(const float*)d_in[3],  (const float*)d_in[7],  (const float*)d_in[11]};
    const float* Whh[3] = {(const float*)d_in[4],  (const float*)d_in[8],  (const float*)d_in[12]};
    const float* bih[3] = {(const float*)d_in[5],  (const float*)d_in[9],  (const float*)d_in[13]};
    const float* bhh[3] = {(const float*)d_in[6],  (const float*)d_in[10], (const float*)d_in[14]};
    const float* Wout1 = (const float*)d_in[15];
    const float* bout1 = (const float*)d_in[16];
    const float* ln_g  = (const float*)d_in[17];
    const float* ln_b  = (const float*)d_in[18];
    const float* Wout2 = (const float*)d_in[19];
    const float* bout2 = (const float*)d_in[20];
    float* out = (float*)d_out;

    float *pX0, *pXa, *pXb, *pxg, *pagg, *pt1, *pt2;
    uint32_t* pWtf;
    cudaGetSymbolAddress((void**)&pX0,  g_X0);
    cudaGetSymbolAddress((void**)&pXa,  g_Xa);
    cudaGetSymbolAddress((void**)&pXb,  g_Xb);
    cudaGetSymbolAddress((void**)&pxg,  g_xg);
    cudaGetSymbolAddress((void**)&pagg, g_agg);
    cudaGetSymbolAddress((void**)&pt1,  g_t1);
    cudaGetSymbolAddress((void**)&pt2,  g_t2);
    cudaGetSymbolAddress((void**)&pWtf, g_Wtf);

    // tf32 weight slabs
    uint32_t* wtf_ih[3] = {pWtf, pWtf + 65536, pWtf + 65536 + 262144};
    uint32_t* wtf_o1 = pWtf + 65536 + 2 * 262144;
    uint32_t* wtf_o2 = wtf_o1 + 393216;
    const int n_ih[3] = {65536, 262144, 262144};

    constexpr int LSTM_SMEM = 128 * 64 * 16 + 2 * 10 * 2 * 128 * 2 * 4;  // 172032
    cudaFuncSetAttribute(lstm_layer,
                         cudaFuncAttributeMaxDynamicSharedMemorySize, LSTM_SMEM);
    cudaFuncSetAttribute(tf32_gemm,
                         cudaFuncAttributeMaxDynamicSharedMemorySize, GEMM_SMEM);

    reset_flags<<<5, 256>>>();
    for (int l = 0; l < 3; l++)
        conv_tf32<<<(n_ih[l] + 255) / 256, 256>>>(Wih[l], wtf_ih[l], n_ih[l]);
    conv_tf32<<<(393216 + 255) / 256, 256>>>(Wout1, wtf_o1, 393216);
    conv_tf32<<<(131072 + 255) / 256, 256>>>(Wout2, wtf_o2, 131072);

    inproj_kernel<<<(NR * 64) / 256, 256>>>(imu, W_in, b_in);

    float* Xin  = pX0;
    int    Kin  = 64;
    float* Xout = pXa;
    for (int layer = 0; layer < 3; layer++) {
        tf32_gemm<<<dim3(8, NR / 128), 256, GEMM_SMEM>>>(
            Xin, (const float*)wtf_ih[layer], pxg, bih[layer], bhh[layer],
            NR, G4, Kin,
            (long long)Kin * G4, (long long)NR * G4, (long long)G4, 4, 1, 1, 1);
        lstm_layer<<<128, 640, LSTM_SMEM>>>(Whh[layer], pxg, Xout, layer,
                                            layer < 2 ? 1 : 0);
        Xin = Xout;
        Kin = 256;
        Xout = (Xin == pXa) ? pXb : pXa;
    }
    float* Xfinal = Xin;

    agg_kernel<<<NSEQ, 256>>>(Xfinal);
    tf32_gemm<<<dim3(4, NSEQ / 128), 256, GEMM_SMEM>>>(
        pagg, (const float*)wtf_o1, pt1, bout1, nullptr,
        NSEQ, 512, 768, 0, 0, 0, 4, 0, 0, 1);
    ln_relu<<<NSEQ, 256>>>(pt1, pt2, ln_g, ln_b);
    tf32_gemm<<<dim3(2, NSEQ / 128), 256, GEMM_SMEM>>>(
        pt2, (const float*)wtf_o2, out, bout2, nullptr,
        NSEQ, 256, 512, 0, 0, 0, 2, 0, 0, 1);
}

// round 11
// speedup vs baseline: 1.0279x; 1.0279x over previous
#include <cuda_runtime.h>
#include <math.h>
#include <stdint.h>

// Problem constants
constexpr int Lc    = 50;
constexpr int NSEQ  = 32 * 40;     // 1280 sequences
constexpr int NR    = NSEQ * Lc;   // 64000 (seq,time) rows
constexpr int H     = 128;
constexpr int G4    = 512;         // 4*H gates

// ---------------------------------------------------------------------------
// Device scratch
// ---------------------------------------------------------------------------
__device__ float g_X0[(size_t)NR * 64];
__device__ float g_Xa[(size_t)NR * 256];
__device__ float g_Xb[(size_t)NR * 256];
__device__ float g_xg[2][(size_t)NR * G4];   // t-major: [dir][t][seq][512]
__device__ float g_hbuf[2][2][NSEQ * H];     // [step parity][dir][row*H+col]
__device__ int   g_flags[2][2][32][8];       // [dir][jtile][rowgroup][rg]
__device__ float g_agg[(size_t)NSEQ * 768];
__device__ float g_t1[(size_t)NSEQ * 512];
__device__ float g_t2[(size_t)NSEQ * 512];
// pre-converted tf32 weights: wih0 | wih1 | wih2 | wout1 | wout2
__device__ uint32_t g_Wtf[65536 + 262144 + 262144 + 393216 + 131072];

// ---------------------------------------------------------------------------
// helpers
// ---------------------------------------------------------------------------
__device__ __forceinline__ float2 ffma2(float2 a, float2 b, float2 c) {
    unsigned long long ud;
    asm("fma.rn.f32x2 %0, %1, %2, %3;"
        : "=l"(ud)
        : "l"(*(unsigned long long*)&a),
          "l"(*(unsigned long long*)&b),
          "l"(*(unsigned long long*)&c));
    float2 d; *(unsigned long long*)&d = ud; return d;
}
__device__ __forceinline__ float2 pack2(float lo, float hi) {
    float2 r; r.x = lo; r.y = hi; return r;
}
__device__ __forceinline__ float sigm_(float x) {
    return __fdividef(1.0f, 1.0f + __expf(-x));
}
__device__ __forceinline__ float tanh_(float x) {
    return __fdividef(2.0f, 1.0f + __expf(-2.0f * x)) - 1.0f;
}
__device__ __forceinline__ uint32_t f2tf(float x) {
    uint32_t r;
    asm("cvt.rna.tf32.f32 %0, %1;" : "=r"(r) : "f"(x));
    return r;
}
__device__ __forceinline__ uint32_t cvsel(float x, int pre) {
    return pre ? __float_as_uint(x) : f2tf(x);
}
__device__ __forceinline__ void mma_tf32(float* d, const uint32_t* a,
                                         const uint32_t* b) {
    asm volatile(
        "mma.sync.aligned.m16n8k8.row.col.f32.tf32.tf32.f32 "
        "{%0,%1,%2,%3}, {%4,%5,%6,%7}, {%8,%9}, {%0,%1,%2,%3};\n"
        : "+f"(d[0]), "+f"(d[1]), "+f"(d[2]), "+f"(d[3])
        : "r"(a[0]), "r"(a[1]), "r"(a[2]), "r"(a[3]), "r"(b[0]), "r"(b[1]));
}

// ---------------------------------------------------------------------------
// reset pairwise-sync flags (once per replay): 2*2*32*8 = 1024 ints
// ---------------------------------------------------------------------------
__global__ void reset_flags() {
    ((int*)g_flags)[blockIdx.x * 256 + threadIdx.x] = 0;
}

// ---------------------------------------------------------------------------
// weight -> tf32 pre-conversion (batched: up to 3 segments per launch)
// ---------------------------------------------------------------------------
__global__ __launch_bounds__(256) void conv_tf32_3(
    const float* __restrict__ s0, uint32_t* __restrict__ d0, int n0,
    const float* __restrict__ s1, uint32_t* __restrict__ d1, int n1,
    const float* __restrict__ s2, uint32_t* __restrict__ d2, int n2)
{
    int i = blockIdx.x * 256 + threadIdx.x;
    if (i < n0) d0[i] = f2tf(s0[i]);
    if (i < n1) d1[i] = f2tf(s1[i]);
    if (i < n2) d2[i] = f2tf(s2[i]);
}

// ---------------------------------------------------------------------------
// Kernel 1: input projection (output pre-rounded to tf32 — feeds GEMM only)
// ---------------------------------------------------------------------------
__global__ __launch_bounds__(256) void inproj_kernel(
    const float* __restrict__ imu, const float* __restrict__ Win,
    const float* __restrict__ bin)
{
    int idx = blockIdx.x * 256 + threadIdx.x;
    int row = idx >> 6;
    int jj  = idx & 63;
    int l   = row % Lc;
    const float* xr = imu + (size_t)row * 6;
    float t    = (float)l * (1.0f / 49.0f);
    float rate = 1.0f;
    float acc = bin[jj];
#pragma unroll
    for (int k = 0; k < 6; k++) acc = fmaf(xr[k], Win[k * 64 + jj], acc);
    acc = fmaf(t,    Win[6 * 64 + jj], acc);
    acc = fmaf(rate, Win[7 * 64 + jj], acc);
    g_X0[(size_t)row * 64 + jj] = __uint_as_float(f2tf(fmaxf(acc, 0.0f)));
}

// ---------------------------------------------------------------------------
// Kernel 2: tf32 tensor-core GEMM + bias. permute: t-major output rows.
// atf/btf: A/B already tf32-rounded (skip cvt).
// ---------------------------------------------------------------------------
constexpr int APITCH = 132;
constexpr int BPITCH = 260;
constexpr int ASZ = 4 * 8 * APITCH;
constexpr int BSZ = 4 * 4 * BPITCH;
constexpr int GEMM_SMEM = (2 * ASZ + 2 * BSZ) * 4;

__device__ __forceinline__ int asI(int buf, int ks, int c, int q) {
    return ((buf * 4 + ks) * 8 + c) * APITCH + q;
}
__device__ __forceinline__ int bsI(int buf, int ks, int kp, int q) {
    return ((buf * 4 + ks) * 4 + kp) * BPITCH + q;
}

__global__ __launch_bounds__(256) void tf32_gemm(
    const float* __restrict__ A, const float* __restrict__ B,
    float* __restrict__ C,
    const float* __restrict__ bias1, const float* __restrict__ bias2,
    int M, int N, int K,
    long long sB, long long sC, long long sBias, int nbx, int permute,
    int atf, int btf)
{
    extern __shared__ uint32_t sm[];
    uint32_t* As = sm;
    uint32_t* Bs = sm + 2 * ASZ;

    const int dir = blockIdx.x / nbx;
    const int nb  = blockIdx.x % nbx;
    const int mb  = blockIdx.y;
    B += (size_t)dir * sB;
    C += (size_t)dir * sC;
    const float* b1 = bias1 + (size_t)dir * sBias;
    const float* b2 = bias2 ? bias2 + (size_t)dir * sBias : nullptr;
    const bool hasB2 = (b2 != nullptr);

    const int tid  = threadIdx.x;
    const int warp = tid >> 5, lane = tid & 31;
    const int wR = warp >> 2, wC = warp & 3;
    const int g  = lane >> 2, tig = lane & 3;

    const float* Ab = A + (size_t)(mb * 128) * K;
    const float* Bb = B + nb * 128;

    const int lr  = tid >> 3;
    const int lc4 = (tid & 7) * 4;
    const int aks = lc4 >> 3, ac0 = lc4 & 7;
    const int bks = lr >> 3, br8 = lr & 7;
    const int bkp = br8 & 3, bhalf = br8 >> 2;

    float acc[4][4][4];
#pragma unroll
    for (int mt = 0; mt < 4; mt++)
#pragma unroll
        for (int nt = 0; nt < 4; nt++)
#pragma unroll
            for (int q = 0; q < 4; q++) acc[mt][nt][q] = 0.0f;

    const int niter = K / 32;

    {
#pragma unroll
        for (int i = 0; i < 4; i++) {
            int r = lr + i * 32;
            float4 v = *(const float4*)(Ab + (size_t)r * K + lc4);
            int q = ((r >> 4) << 4) + ((r & 7) << 1) + ((r >> 3) & 1);
            uint32_t* d = &As[asI(0, aks, ac0, q)];
            d[0] = cvsel(v.x, atf); d[APITCH] = cvsel(v.y, atf);
            d[2 * APITCH] = cvsel(v.z, atf); d[3 * APITCH] = cvsel(v.w, atf);
        }
#pragma unroll
        for (int i = 0; i < 4; i++) {
            int col = lc4 + i * 32;
            float4 v = *(const float4*)(Bb + (size_t)lr * N + col);
            uint32_t* d = &Bs[bsI(0, bks, bkp, col * 2 + bhalf)];
            d[0] = cvsel(v.x, btf); d[2] = cvsel(v.y, btf);
            d[4] = cvsel(v.z, btf); d[6] = cvsel(v.w, btf);
        }
    }
    __syncthreads();

    for (int it = 0; it < niter; it++) {
        const int cur = it & 1, nxt = cur ^ 1;
        const bool more = (it + 1 < niter);
        float4 av[4], bv[4];
        if (more) {
            int k0 = (it + 1) * 32;
#pragma unroll
            for (int i = 0; i < 4; i++) {
                av[i] = *(const float4*)(Ab + (size_t)(lr + i * 32) * K + k0 + lc4);
                bv[i] = *(const float4*)(Bb + (size_t)(k0 + lr) * N + lc4 + i * 32);
            }
        }

#pragma unroll
        for (int ks = 0; ks < 4; ks++) {
            uint32_t af[4][4];
#pragma unroll
            for (int mt = 0; mt < 4; mt++) {
                int q = ((wR * 4 + mt) << 4) + (g << 1);
                uint2 u0 = *(const uint2*)&As[asI(cur, ks, tig, q)];
                uint2 u1 = *(const uint2*)&As[asI(cur, ks, tig + 4, q)];
                af[mt][0] = u0.x; af[mt][1] = u0.y;
                af[mt][2] = u1.x; af[mt][3] = u1.y;
            }
            uint32_t bf[4][2];
#pragma unroll
            for (int nt = 0; nt < 4; nt++) {
                int n = wC * 32 + nt * 8 + g;
                uint2 u = *(const uint2*)&Bs[bsI(cur, ks, tig, n * 2)];
                bf[nt][0] = u.x; bf[nt][1] = u.y;
            }
#pragma unroll
            for (int mt = 0; mt < 4; mt++)
#pragma unroll
                for (int nt = 0; nt < 4; nt++)
                    mma_tf32(acc[mt][nt], af[mt], bf[nt]);
        }

        if (more) {
#pragma unroll
            for (int i = 0; i < 4; i++) {
                int r = lr + i * 32;
                int q = ((r >> 4) << 4) + ((r & 7) << 1) + ((r >> 3) & 1);
                uint32_t* d = &As[asI(nxt, aks, ac0, q)];
                d[0] = cvsel(av[i].x, atf); d[APITCH] = cvsel(av[i].y, atf);
                d[2 * APITCH] = cvsel(av[i].z, atf); d[3 * APITCH] = cvsel(av[i].w, atf);
                int col = lc4 + i * 32;
                uint32_t* db = &Bs[bsI(nxt, bks, bkp, col * 2 + bhalf)];
                db[0] = cvsel(bv[i].x, btf); db[2] = cvsel(bv[i].y, btf);
                db[4] = cvsel(bv[i].z, btf); db[6] = cvsel(bv[i].w, btf);
            }
        }
        __syncthreads();
    }

#pragma unroll
    for (int mt = 0; mt < 4; mt++) {
        int rowa = mb * 128 + wR * 64 + mt * 16 + g;
        int rowb = rowa + 8;
        size_t ra = permute ? ((size_t)(rowa % Lc) * NSEQ + rowa / Lc) : (size_t)rowa;
        size_t rb = permute ? ((size_t)(rowb % Lc) * NSEQ + rowb / Lc) : (size_t)rowb;
#pragma unroll
        for (int nt = 0; nt < 4; nt++) {
            int colg = nb * 128 + wC * 32 + nt * 8 + 2 * tig;
            float bx = b1[colg], by = b1[colg + 1];
            if (hasB2) { bx += b2[colg]; by += b2[colg + 1]; }
            float2 v0 = pack2(acc[mt][nt][0] + bx, acc[mt][nt][1] + by);
            float2 v1 = pack2(acc[mt][nt][2] + bx, acc[mt][nt][3] + by);
            *(float2*)(C + ra * N + colg) = v0;
            *(float2*)(C + rb * N + colg) = v1;
        }
    }
}

// ---------------------------------------------------------------------------
// Kernel 3: PERSISTENT BiLSTM layer — round-8 winner configuration.
// 128 CTAs x 512 threads. CTA = (dir, jt, rowgroup of 40 rows).
// warp = (rg 0..7, jh 0..1); rg pair (64 threads) owns 5 rows; sync via
// named barrier id=rg + per-rg release/acquire flags. Simple k-loop.
// roundout: store Xout pre-rounded to tf32 when it only feeds a GEMM.
// ---------------------------------------------------------------------------
#define BARRG(rgid) asm volatile("bar.sync %0, 64;" :: "r"(rgid) : "memory")

__global__ __launch_bounds__(512) void lstm_layer(
    const float* __restrict__ Whh,
    const float* __restrict__ xgb,   // t-major [dir][t][seq][512]
    float* __restrict__ Xout,
    int layer, int roundout)
{
    extern __shared__ float smem[];
    float4* ws  = (float4*)smem;                 // [128][64] gate quads
    float*  hsf = smem + 128 * 64 * 4;
    constexpr int RGSZ = 3 * 128 * 2;            // floats per rg slice
    constexpr int HBUF = 8 * RGSZ;               // floats per buffer

    const int bx   = blockIdx.x;
    const int dir  = bx >> 6;
    const int jt   = (bx >> 5) & 1;
    const int rgI  = bx & 31;
    const int row0 = rgI * 40;
    const int tid  = threadIdx.x;
    const int warp = tid >> 5, lane = tid & 31;
    const int rg   = warp >> 1, jh = warp & 1;
    const int jcol = (jh << 5) + lane;           // 0..63
    const int col  = (jt << 6) + jcol;           // 0..127
    const int rbase = row0 + rg * 5;
    const int base = layer * Lc;
    const bool leader = (jh == 0 && lane == 0);

    const float* W   = Whh + (size_t)dir * (H * G4);
    const float* xgd = xgb + (size_t)dir * NR * G4;
    int* myflag = &g_flags[dir][jt][rgI][rg];
    int* pflag  = &g_flags[dir][jt ^ 1][rgI][rg];

    for (int idx = tid; idx < 128 * 64; idx += 512) {
        int k = idx >> 6, j = idx & 63;
        const float* wk = W + (size_t)k * G4 + (jt << 6) + j;
        ws[idx] = make_float4(wk[0], wk[128], wk[256], wk[384]);
    }
    __syncthreads();

    float c[5];
#pragma unroll
    for (int r = 0; r < 5; r++) c[r] = 0.0f;

    for (int step = 0; step < Lc; step++) {
        const int tin = dir ? (Lc - 1 - step) : step;

        // xg loads (t-major: contiguous region per step)
        float2 acc2[4][2];
        float  accs[4];
        const float* xp = xgd + ((size_t)tin * NSEQ + rbase) * G4 + col;
#pragma unroll
        for (int p = 0; p < 2; p++) {
            const float* xa = xp + (size_t)(2 * p) * G4;
            const float* xb = xa + G4;
#pragma unroll
            for (int gi = 0; gi < 4; gi++)
                acc2[gi][p] = pack2(xa[gi * 128], xb[gi * 128]);
        }
        {
            const float* xa = xp + (size_t)4 * G4;
#pragma unroll
            for (int gi = 0; gi < 4; gi++) accs[gi] = xa[gi * 128];
        }

        if (step > 0) {
            if (leader) {
                const int want = base + step;
                int v;
                do {
                    asm volatile("ld.acquire.gpu.global.b32 %0, [%1];"
                                 : "=r"(v) : "l"(pflag) : "memory");
                } while (v < want);
            }
            BARRG(rg);

            // restage partner half (this rg's 5 rows, this warp's 32 cols)
            {
                const float* hbg = g_hbuf[(step + 1) & 1][dir];
                float* hc = hsf + ((step + 1) & 1) * HBUF + rg * RGSZ;
                int pc = ((jt ^ 1) << 6) + jcol;
#pragma unroll
                for (int r = 0; r < 5; r++)
                    hc[(((r >> 1) << 7) + pc) * 2 + (r & 1)] =
                        hbg[(size_t)(rbase + r) * H + pc];
            }
            BARRG(rg);

            // k-loop
            const float*  hrow  = hsf + ((step + 1) & 1) * HBUF + rg * RGSZ;
            const float2* hrow2 = (const float2*)hrow;
#pragma unroll 8
            for (int k = 0; k < 128; k++) {
                float4 w4 = ws[(k << 6) + jcol];
                float2 ha = hrow2[k];
                float2 hb = hrow2[128 + k];
                float  hc = hrow[(256 + k) * 2];
                float2 w0 = pack2(w4.x, w4.x);
                float2 w1 = pack2(w4.y, w4.y);
                float2 w2 = pack2(w4.z, w4.z);
                float2 w3 = pack2(w4.w, w4.w);
                acc2[0][0] = ffma2(ha, w0, acc2[0][0]);
                acc2[1][0] = ffma2(ha, w1, acc2[1][0]);
                acc2[2][0] = ffma2(ha, w2, acc2[2][0]);
                acc2[3][0] = ffma2(ha, w3, acc2[3][0]);
                acc2[0][1] = ffma2(hb, w0, acc2[0][1]);
                acc2[1][1] = ffma2(hb, w1, acc2[1][1]);
                acc2[2][1] = ffma2(hb, w2, acc2[2][1]);
                acc2[3][1] = ffma2(hb, w3, acc2[3][1]);
                accs[0] = fmaf(hc, w4.x, accs[0]);
                accs[1] = fmaf(hc, w4.y, accs[1]);
                accs[2] = fmaf(hc, w4.z, accs[2]);
                accs[3] = fmaf(hc, w4.w, accs[3]);
            }
        }

        // gates + state update
        float hval[5];
#pragma unroll
        for (int p = 0; p < 2; p++) {
            float i0 = sigm_(acc2[0][p].x), i1 = sigm_(acc2[0][p].y);
            float f0 = sigm_(acc2[1][p].x), f1 = sigm_(acc2[1][p].y);
            float ga = tanh_(acc2[2][p].x), gb = tanh_(acc2[2][p].y);
            float o0 = sigm_(acc2[3][p].x), o1 = sigm_(acc2[3][p].y);
            float c0 = fmaf(f0, c[2 * p],     i0 * ga);
            float c1 = fmaf(f1, c[2 * p + 1], i1 * gb);
            c[2 * p] = c0; c[2 * p + 1] = c1;
            hval[2 * p]     = o0 * tanh_(c0);
            hval[2 * p + 1] = o1 * tanh_(c1);
        }
        {
            float ig = sigm_(accs[0]);
            float fg = sigm_(accs[1]);
            float gg = tanh_(accs[2]);
            float og = sigm_(accs[3]);
            float cn = fmaf(fg, c[4], ig * gg);
            c[4] = cn;
            hval[4] = og * tanh_(cn);
        }

        // publish own half: local smem + global for partner, then flag
        if (step < Lc - 1) {
            float* hw  = hsf + (step & 1) * HBUF + rg * RGSZ;
            float* hbw = g_hbuf[step & 1][dir];
#pragma unroll
            for (int r = 0; r < 5; r++) {
                hw[(((r >> 1) << 7) + col) * 2 + (r & 1)] = hval[r];
                hbw[(size_t)(rbase + r) * H + col] = hval[r];
            }
            BARRG(rg);
            if (leader) {
                int dummy;
                asm volatile("atom.release.gpu.global.exch.b32 %0, [%1], %2;"
                             : "=r"(dummy) : "l"(myflag), "r"(base + step + 1)
                             : "memory");
            }
        }

        // layer output
#pragma unroll
        for (int r = 0; r < 5; r++) {
            float v = hval[r];
            if (roundout) v = __uint_as_float(f2tf(v));
            Xout[((size_t)(rbase + r) * Lc + tin) * 256 + dir * H + col] = v;
        }
    }
}

// ---------------------------------------------------------------------------
// Kernel 4: aggregation
// ---------------------------------------------------------------------------
__global__ __launch_bounds__(256) void agg_kernel(const float* __restrict__ X)
{
    int n = blockIdx.x, f = threadIdx.x;
    const float* base = X + (size_t)n * Lc * 256 + f;
    float s = 0.0f, m = -1e30f;
#pragma unroll 5
    for (int l = 0; l < Lc; l++) {
        float v = base[(size_t)l * 256];
        s += v; m = fmaxf(m, v);
    }
    g_agg[(size_t)n * 768 + f]       = s * (1.0f / Lc);
    g_agg[(size_t)n * 768 + 256 + f] = m;
    g_agg[(size_t)n * 768 + 512 + f] = (f < H) ? base[(Lc - 1) * 256] : base[0];
}

// ---------------------------------------------------------------------------
// Kernel 5: LayerNorm(512) + ReLU
// ---------------------------------------------------------------------------
__global__ __launch_bounds__(256) void ln_relu(
    const float* __restrict__ x, float* __restrict__ y,
    const float* __restrict__ gam, const float* __restrict__ bet)
{
    int row = blockIdx.x, tid = threadIdx.x;
    const float* xr = x + (size_t)row * 512;
    float v0 = xr[tid], v1 = xr[tid + 256];
    float s = v0 + v1, q = v0 * v0 + v1 * v1;
    __shared__ float ss[8], sq[8];
#pragma unroll
    for (int o = 16; o > 0; o >>= 1) {
        s += __shfl_down_sync(~0u, s, o);
        q += __shfl_down_sync(~0u, q, o);
    }
    int w = tid >> 5;
    if ((tid & 31) == 0) { ss[w] = s; sq[w] = q; }
    __syncthreads();
    if (tid == 0) {
        float S = 0.0f, Q = 0.0f;
        for (int i = 0; i < 8; i++) { S += ss[i]; Q += sq[i]; }
        ss[0] = S; sq[0] = Q;
    }
    __syncthreads();
    float mu  = ss[0] * (1.0f / 512.0f);
    float var = sq[0] * (1.0f / 512.0f) - mu * mu;
    float rs  = rsqrtf(var + 1e-5f);
    y[(size_t)row * 512 + tid]       = fmaxf((v0 - mu) * rs * gam[tid]       + bet[tid],       0.0f);
    y[(size_t)row * 512 + tid + 256] = fmaxf((v1 - mu) * rs * gam[tid + 256] + bet[tid + 256], 0.0f);
}

// ---------------------------------------------------------------------------
// Host orchestration
// ---------------------------------------------------------------------------
extern "C" void kernel_launch(void* const* d_in, const int* in_sizes, int n_in,
                              void* d_out, int out_size)
{
    const float* imu   = (const float*)d_in[0];
    const float* W_in  = (const float*)d_in[1];
    const float* b_in  = (const float*)d_in[2];
    const float* Wih[3] = {(const float*)d_in[3],  (const float*)d_in[7],  (const float*)d_in[11]};
    const float* Whh[3] = {(const float*)d_in[4],  (const float*)d_in[8],  (const float*)d_in[12]};
    const float* bih[3] = {(const float*)d_in[5],  (const float*)d_in[9],  (const float*)d_in[13]};
    const float* bhh[3] = {(const float*)d_in[6],  (const float*)d_in[10], (const float*)d_in[14]};
    const float* Wout1 = (const float*)d_in[15];
    const float* bout1 = (const float*)d_in[16];
    const float* ln_g  = (const float*)d_in[17];
    const float* ln_b  = (const float*)d_in[18];
    const float* Wout2 = (const float*)d_in[19];
    const float* bout2 = (const float*)d_in[20];
    float* out = (float*)d_out;

    float *pX0, *pXa, *pXb, *pxg, *pagg, *pt1, *pt2;
    uint32_t* pWtf;
    cudaGetSymbolAddress((void**)&pX0,  g_X0);
    cudaGetSymbolAddress((void**)&pXa,  g_Xa);
    cudaGetSymbolAddress((void**)&pXb,  g_Xb);
    cudaGetSymbolAddress((void**)&pxg,  g_xg);
    cudaGetSymbolAddress((void**)&pagg, g_agg);
    cudaGetSymbolAddress((void**)&pt1,  g_t1);
    cudaGetSymbolAddress((void**)&pt2,  g_t2);
    cudaGetSymbolAddress((void**)&pWtf, g_Wtf);

    // tf32 weight slabs
    uint32_t* wtf_ih[3] = {pWtf, pWtf + 65536, pWtf + 65536 + 262144};
    uint32_t* wtf_o1 = pWtf + 65536 + 2 * 262144;
    uint32_t* wtf_o2 = wtf_o1 + 393216;

    constexpr int LSTM_SMEM = 128 * 64 * 16 + 2 * 8 * 3 * 128 * 8;  // 180224
    cudaFuncSetAttribute(lstm_layer,
                         cudaFuncAttributeMaxDynamicSharedMemorySize, LSTM_SMEM);
    cudaFuncSetAttribute(tf32_gemm,
                         cudaFuncAttributeMaxDynamicSharedMemorySize, GEMM_SMEM);

    reset_flags<<<4, 256>>>();
    // weight->tf32 in two batched launches (largest segment bounds grid)
    conv_tf32_3<<<(393216 + 255) / 256, 256>>>(
        Wih[0], wtf_ih[0], 65536,
        Wih[1], wtf_ih[1], 262144,
        Wout1,  wtf_o1,    393216);
    conv_tf32_3<<<(262144 + 255) / 256, 256>>>(
        Wih[2], wtf_ih[2], 262144,
        Wout2,  wtf_o2,    131072,
        nullptr, nullptr,  0);

    inproj_kernel<<<(NR * 64) / 256, 256>>>(imu, W_in, b_in);

    float* Xin  = pX0;
    int    Kin  = 64;
    float* Xout = pXa;
    for (int layer = 0; layer < 3; layer++) {
        tf32_gemm<<<dim3(8, NR / 128), 256, GEMM_SMEM>>>(
            Xin, (const float*)wtf_ih[layer], pxg, bih[layer], bhh[layer],
            NR, G4, Kin,
            (long long)Kin * G4, (long long)NR * G4, (long long)G4, 4, 1, 1, 1);
        lstm_layer<<<128, 512, LSTM_SMEM>>>(Whh[layer], pxg, Xout, layer,
                                            layer < 2 ? 1 : 0);
        Xin = Xout;
        Kin = 256;
        Xout = (Xin == pXa) ? pXb : pXa;
    }
    float* Xfinal = Xin;

    agg_kernel<<<NSEQ, 256>>>(Xfinal);
    tf32_gemm<<<dim3(4, NSEQ / 128), 256, GEMM_SMEM>>>(
        pagg, (const float*)wtf_o1, pt1, bout1, nullptr,
        NSEQ, 512, 768, 0, 0, 0, 4, 0, 0, 1);
    ln_relu<<<NSEQ, 256>>>(pt1, pt2, ln_g, ln_b);
    tf32_gemm<<<dim3(2, NSEQ / 128), 256, GEMM_SMEM>>>(
        pt2, (const float*)wtf_o2, out, bout2, nullptr,
        NSEQ, 256, 512, 0, 0, 0, 2, 0, 0, 1);
}

// round 12
// speedup vs baseline: 1.0489x; 1.0204x over previous
#include <cuda_runtime.h>
#include <math.h>
#include <stdint.h>

// Problem constants
constexpr int Lc    = 50;
constexpr int NSEQ  = 32 * 40;     // 1280 sequences
constexpr int NR    = NSEQ * Lc;   // 64000 (seq,time) rows
constexpr int H     = 128;
constexpr int G4    = 512;         // 4*H gates

// ---------------------------------------------------------------------------
// Device scratch
// ---------------------------------------------------------------------------
__device__ float g_X0[(size_t)NR * 64];
__device__ float g_Xa[(size_t)NR * 256];
__device__ float g_Xb[(size_t)NR * 256];
__device__ float g_xg[2][(size_t)NR * G4];   // t-major: [dir][t][seq][512]
__device__ float g_agg[(size_t)NSEQ * 768];
__device__ float g_t1[(size_t)NSEQ * 512];
__device__ float g_t2[(size_t)NSEQ * 512];

// ---------------------------------------------------------------------------
// helpers
// ---------------------------------------------------------------------------
__device__ __forceinline__ float2 ffma2(float2 a, float2 b, float2 c) {
    unsigned long long ud;
    asm("fma.rn.f32x2 %0, %1, %2, %3;"
        : "=l"(ud)
        : "l"(*(unsigned long long*)&a),
          "l"(*(unsigned long long*)&b),
          "l"(*(unsigned long long*)&c));
    float2 d; *(unsigned long long*)&d = ud; return d;
}
__device__ __forceinline__ float2 pack2(float lo, float hi) {
    float2 r; r.x = lo; r.y = hi; return r;
}
__device__ __forceinline__ float sigm_(float x) {
    return __fdividef(1.0f, 1.0f + __expf(-x));
}
__device__ __forceinline__ float tanh_(float x) {
    return __fdividef(2.0f, 1.0f + __expf(-2.0f * x)) - 1.0f;
}
__device__ __forceinline__ uint32_t f2tf(float x) {
    uint32_t r;
    asm("cvt.rna.tf32.f32 %0, %1;" : "=r"(r) : "f"(x));
    return r;
}
__device__ __forceinline__ void mma_tf32(float* d, const uint32_t* a,
                                         const uint32_t* b) {
    asm volatile(
        "mma.sync.aligned.m16n8k8.row.col.f32.tf32.tf32.f32 "
        "{%0,%1,%2,%3}, {%4,%5,%6,%7}, {%8,%9}, {%0,%1,%2,%3};\n"
        : "+f"(d[0]), "+f"(d[1]), "+f"(d[2]), "+f"(d[3])
        : "r"(a[0]), "r"(a[1]), "r"(a[2]), "r"(a[3]), "r"(b[0]), "r"(b[1]));
}
__device__ __forceinline__ uint32_t smem_u32(const void* p) {
    uint32_t a;
    asm("{ .reg .u64 t; cvta.to.shared.u64 t, %1; cvt.u32.u64 %0, t; }"
        : "=r"(a) : "l"(p));
    return a;
}

// ---------------------------------------------------------------------------
// Kernel 1: input projection
// ---------------------------------------------------------------------------
__global__ __launch_bounds__(256) void inproj_kernel(
    const float* __restrict__ imu, const float* __restrict__ Win,
    const float* __restrict__ bin)
{
    int idx = blockIdx.x * 256 + threadIdx.x;
    int row = idx >> 6;
    int jj  = idx & 63;
    int l   = row % Lc;
    const float* xr = imu + (size_t)row * 6;
    float t    = (float)l * (1.0f / 49.0f);
    float rate = 1.0f;
    float acc = bin[jj];
#pragma unroll
    for (int k = 0; k < 6; k++) acc = fmaf(xr[k], Win[k * 64 + jj], acc);
    acc = fmaf(t,    Win[6 * 64 + jj], acc);
    acc = fmaf(rate, Win[7 * 64 + jj], acc);
    g_X0[(size_t)row * 64 + jj] = fmaxf(acc, 0.0f);
}

// ---------------------------------------------------------------------------
// Kernel 2: tf32 tensor-core GEMM + bias (round-8 proven version).
// permute: t-major output rows. 128x128x32 tiles, 8 warps, m16n8k8.
// ---------------------------------------------------------------------------
constexpr int APITCH = 132;
constexpr int BPITCH = 260;
constexpr int ASZ = 4 * 8 * APITCH;
constexpr int BSZ = 4 * 4 * BPITCH;
constexpr int GEMM_SMEM = (2 * ASZ + 2 * BSZ) * 4;

__device__ __forceinline__ int asI(int buf, int ks, int c, int q) {
    return ((buf * 4 + ks) * 8 + c) * APITCH + q;
}
__device__ __forceinline__ int bsI(int buf, int ks, int kp, int q) {
    return ((buf * 4 + ks) * 4 + kp) * BPITCH + q;
}

__global__ __launch_bounds__(256) void tf32_gemm(
    const float* __restrict__ A, const float* __restrict__ B,
    float* __restrict__ C,
    const float* __restrict__ bias1, const float* __restrict__ bias2,
    int M, int N, int K,
    long long sB, long long sC, long long sBias, int nbx, int permute)
{
    extern __shared__ uint32_t sm[];
    uint32_t* As = sm;
    uint32_t* Bs = sm + 2 * ASZ;

    const int dir = blockIdx.x / nbx;
    const int nb  = blockIdx.x % nbx;
    const int mb  = blockIdx.y;
    B += (size_t)dir * sB;
    C += (size_t)dir * sC;
    const float* b1 = bias1 + (size_t)dir * sBias;
    const float* b2 = bias2 ? bias2 + (size_t)dir * sBias : nullptr;
    const bool hasB2 = (b2 != nullptr);

    const int tid  = threadIdx.x;
    const int warp = tid >> 5, lane = tid & 31;
    const int wR = warp >> 2, wC = warp & 3;
    const int g  = lane >> 2, tig = lane & 3;

    const float* Ab = A + (size_t)(mb * 128) * K;
    const float* Bb = B + nb * 128;

    const int lr  = tid >> 3;
    const int lc4 = (tid & 7) * 4;
    const int aks = lc4 >> 3, ac0 = lc4 & 7;
    const int bks = lr >> 3, br8 = lr & 7;
    const int bkp = br8 & 3, bhalf = br8 >> 2;

    float acc[4][4][4];
#pragma unroll
    for (int mt = 0; mt < 4; mt++)
#pragma unroll
        for (int nt = 0; nt < 4; nt++)
#pragma unroll
            for (int q = 0; q < 4; q++) acc[mt][nt][q] = 0.0f;

    const int niter = K / 32;

    {
#pragma unroll
        for (int i = 0; i < 4; i++) {
            int r = lr + i * 32;
            float4 v = *(const float4*)(Ab + (size_t)r * K + lc4);
            int q = ((r >> 4) << 4) + ((r & 7) << 1) + ((r >> 3) & 1);
            uint32_t* d = &As[asI(0, aks, ac0, q)];
            d[0] = f2tf(v.x); d[APITCH] = f2tf(v.y);
            d[2 * APITCH] = f2tf(v.z); d[3 * APITCH] = f2tf(v.w);
        }
#pragma unroll
        for (int i = 0; i < 4; i++) {
            int col = lc4 + i * 32;
            float4 v = *(const float4*)(Bb + (size_t)lr * N + col);
            uint32_t* d = &Bs[bsI(0, bks, bkp, col * 2 + bhalf)];
            d[0] = f2tf(v.x); d[2] = f2tf(v.y);
            d[4] = f2tf(v.z); d[6] = f2tf(v.w);
        }
    }
    __syncthreads();

    for (int it = 0; it < niter; it++) {
        const int cur = it & 1, nxt = cur ^ 1;
        const bool more = (it + 1 < niter);
        float4 av[4], bv[4];
        if (more) {
            int k0 = (it + 1) * 32;
#pragma unroll
            for (int i = 0; i < 4; i++) {
                av[i] = *(const float4*)(Ab + (size_t)(lr + i * 32) * K + k0 + lc4);
                bv[i] = *(const float4*)(Bb + (size_t)(k0 + lr) * N + lc4 + i * 32);
            }
        }

#pragma unroll
        for (int ks = 0; ks < 4; ks++) {
            uint32_t af[4][4];
#pragma unroll
            for (int mt = 0; mt < 4; mt++) {
                int q = ((wR * 4 + mt) << 4) + (g << 1);
                uint2 u0 = *(const uint2*)&As[asI(cur, ks, tig, q)];
                uint2 u1 = *(const uint2*)&As[asI(cur, ks, tig + 4, q)];
                af[mt][0] = u0.x; af[mt][1] = u0.y;
                af[mt][2] = u1.x; af[mt][3] = u1.y;
            }
            uint32_t bf[4][2];
#pragma unroll
            for (int nt = 0; nt < 4; nt++) {
                int n = wC * 32 + nt * 8 + g;
                uint2 u = *(const uint2*)&Bs[bsI(cur, ks, tig, n * 2)];
                bf[nt][0] = u.x; bf[nt][1] = u.y;
            }
#pragma unroll
            for (int mt = 0; mt < 4; mt++)
#pragma unroll
                for (int nt = 0; nt < 4; nt++)
                    mma_tf32(acc[mt][nt], af[mt], bf[nt]);
        }

        if (more) {
#pragma unroll
            for (int i = 0; i < 4; i++) {
                int r = lr + i * 32;
                int q = ((r >> 4) << 4) + ((r & 7) << 1) + ((r >> 3) & 1);
                uint32_t* d = &As[asI(nxt, aks, ac0, q)];
                d[0] = f2tf(av[i].x); d[APITCH] = f2tf(av[i].y);
                d[2 * APITCH] = f2tf(av[i].z); d[3 * APITCH] = f2tf(av[i].w);
                int col = lc4 + i * 32;
                uint32_t* db = &Bs[bsI(nxt, bks, bkp, col * 2 + bhalf)];
                db[0] = f2tf(bv[i].x); db[2] = f2tf(bv[i].y);
                db[4] = f2tf(bv[i].z); db[6] = f2tf(bv[i].w);
            }
        }
        __syncthreads();
    }

#pragma unroll
    for (int mt = 0; mt < 4; mt++) {
        int rowa = mb * 128 + wR * 64 + mt * 16 + g;
        int rowb = rowa + 8;
        size_t ra = permute ? ((size_t)(rowa % Lc) * NSEQ + rowa / Lc) : (size_t)rowa;
        size_t rb = permute ? ((size_t)(rowb % Lc) * NSEQ + rowb / Lc) : (size_t)rowb;
#pragma unroll
        for (int nt = 0; nt < 4; nt++) {
            int colg = nb * 128 + wC * 32 + nt * 8 + 2 * tig;
            float bx = b1[colg], by = b1[colg + 1];
            if (hasB2) { bx += b2[colg]; by += b2[colg + 1]; }
            float2 v0 = pack2(acc[mt][nt][0] + bx, acc[mt][nt][1] + by);
            float2 v1 = pack2(acc[mt][nt][2] + bx, acc[mt][nt][3] + by);
            *(float2*)(C + ra * N + colg) = v0;
            *(float2*)(C + rb * N + colg) = v1;
        }
    }
}

// ---------------------------------------------------------------------------
// Kernel 3: PERSISTENT BiLSTM layer — DSMEM push exchange.
// 128 CTAs (64 clusters of 2) x 512 threads. bx = dir*64 + rgI*2 + jt, so
// cluster = jt-partner pair. CTA owns 40 rows x 64 cols (jt half).
// warp = (rg 0..7, jh 0..1); rg pair (64 threads) owns 5 rows.
// Per step each rg: writes its h half into its OWN hs buffer AND the
// partner CTA's hs buffer (st.shared::cluster), then does a release
// mbarrier.arrive on the partner's per-rg mbarrier (64 arrivals/phase).
// Consumer spins on its LOCAL mbarrier (try_wait.parity.acquire.cluster).
// No global h traffic, no per-step cluster barrier.
// ---------------------------------------------------------------------------
#define BARRG(rgid) asm volatile("bar.sync %0, 64;" :: "r"(rgid) : "memory")

constexpr int RGSZ = 3 * 128 * 2;              // floats per rg slice
constexpr int HBUF = 8 * RGSZ;                 // floats per h buffer
constexpr int LSTM_SMEM = 128 * 64 * 16        // ws
                        + 2 * HBUF * 4         // double-buffered h
                        + 8 * 8;               // 8 mbarriers

__global__ __launch_bounds__(512) __cluster_dims__(2, 1, 1)
void lstm_layer(const float* __restrict__ Whh,
                const float* __restrict__ xgb,   // t-major [dir][t][seq][512]
                float* __restrict__ Xout)
{
    extern __shared__ float smem[];
    float4* ws  = (float4*)smem;                 // [128][64] gate quads
    float*  hsf = smem + 128 * 64 * 4;           // 2 x HBUF
    unsigned long long* mbar =
        (unsigned long long*)(hsf + 2 * HBUF);   // [8] per-rg mbarriers

    const int bx   = blockIdx.x;
    const int dir  = bx >> 6;
    const int jt   = bx & 1;                     // cluster rank
    const int rgI  = (bx >> 1) & 31;
    const int row0 = rgI * 40;
    const int tid  = threadIdx.x;
    const int warp = tid >> 5, lane = tid & 31;
    const int rg   = warp >> 1, jh = warp & 1;
    const int jcol = (jh << 5) + lane;           // 0..63
    const int col  = (jt << 6) + jcol;           // 0..127
    const int rbase = row0 + rg * 5;

    const float* W   = Whh + (size_t)dir * (H * G4);
    const float* xgd = xgb + (size_t)dir * NR * G4;

    // init per-rg mbarriers (count = 64 partner arrivals per phase)
    if (tid < 8) {
        uint32_t mb = smem_u32(&mbar[tid]);
        asm volatile("mbarrier.init.shared.b64 [%0], %1;"
                     :: "r"(mb), "r"(64) : "memory");
    }

    // stage Whh slice: ws[k*64+j] = {W[k][jt*64+j + g*128]}
    for (int idx = tid; idx < 128 * 64; idx += 512) {
        int k = idx >> 6, j = idx & 63;
        const float* wk = W + (size_t)k * G4 + (jt << 6) + j;
        ws[idx] = make_float4(wk[0], wk[128], wk[256], wk[384]);
    }
    __syncthreads();
    // cluster rendezvous: mbarrier init visible + partner smem alive
    asm volatile("barrier.cluster.arrive.aligned;" ::: "memory");
    asm volatile("barrier.cluster.wait.aligned;" ::: "memory");

    // remote addresses in partner CTA
    const uint32_t mb_l = smem_u32(&mbar[rg]);
    uint32_t mb_r;
    asm("mapa.shared::cluster.u32 %0, %1, %2;"
        : "=r"(mb_r) : "r"(mb_l), "r"(jt ^ 1));
    const uint32_t hs_l = smem_u32(hsf);
    uint32_t hs_r;
    asm("mapa.shared::cluster.u32 %0, %1, %2;"
        : "=r"(hs_r) : "r"(hs_l), "r"(jt ^ 1));

    float c[5];
#pragma unroll
    for (int r = 0; r < 5; r++) c[r] = 0.0f;

    for (int step = 0; step < Lc; step++) {
        const int tin = dir ? (Lc - 1 - step) : step;

        // xg loads (t-major: contiguous region per step)
        float2 acc2[4][2];
        float  accs[4];
        const float* xp = xgd + ((size_t)tin * NSEQ + rbase) * G4 + col;
#pragma unroll
        for (int p = 0; p < 2; p++) {
            const float* xa = xp + (size_t)(2 * p) * G4;
            const float* xb = xa + G4;
#pragma unroll
            for (int gi = 0; gi < 4; gi++)
                acc2[gi][p] = pack2(xa[gi * 128], xb[gi * 128]);
        }
        {
            const float* xa = xp + (size_t)4 * G4;
#pragma unroll
            for (int gi = 0; gi < 4; gi++) accs[gi] = xa[gi * 128];
        }

        if (step > 0) {
            // wait for partner's h(step-1): local mbarrier, phase = step-1
            {
                const uint32_t parity = (uint32_t)((step - 1) & 1);
                uint32_t done;
                do {
                    asm volatile(
                        "{\n\t.reg .pred p;\n\t"
                        "mbarrier.try_wait.parity.acquire.cluster.shared::cta.b64 "
                        "p, [%1], %2;\n\t"
                        "selp.b32 %0, 1, 0, p;\n\t}"
                        : "=r"(done) : "r"(mb_l), "r"(parity) : "memory");
                } while (!done);
            }

            // k-loop over h(step-1) in buffer (step-1)&1
            const float*  hrow  = hsf + ((step + 1) & 1) * HBUF + rg * RGSZ;
            const float2* hrow2 = (const float2*)hrow;
#pragma unroll 8
            for (int k = 0; k < 128; k++) {
                float4 w4 = ws[(k << 6) + jcol];
                float2 ha = hrow2[k];
                float2 hb = hrow2[128 + k];
                float  hc = hrow[(256 + k) * 2];
                float2 w0 = pack2(w4.x, w4.x);
                float2 w1 = pack2(w4.y, w4.y);
                float2 w2 = pack2(w4.z, w4.z);
                float2 w3 = pack2(w4.w, w4.w);
                acc2[0][0] = ffma2(ha, w0, acc2[0][0]);
                acc2[1][0] = ffma2(ha, w1, acc2[1][0]);
                acc2[2][0] = ffma2(ha, w2, acc2[2][0]);
                acc2[3][0] = ffma2(ha, w3, acc2[3][0]);
                acc2[0][1] = ffma2(hb, w0, acc2[0][1]);
                acc2[1][1] = ffma2(hb, w1, acc2[1][1]);
                acc2[2][1] = ffma2(hb, w2, acc2[2][1]);
                acc2[3][1] = ffma2(hb, w3, acc2[3][1]);
                accs[0] = fmaf(hc, w4.x, accs[0]);
                accs[1] = fmaf(hc, w4.y, accs[1]);
                accs[2] = fmaf(hc, w4.z, accs[2]);
                accs[3] = fmaf(hc, w4.w, accs[3]);
            }
        }

        // gates + state update
        float hval[5];
#pragma unroll
        for (int p = 0; p < 2; p++) {
            float i0 = sigm_(acc2[0][p].x), i1 = sigm_(acc2[0][p].y);
            float f0 = sigm_(acc2[1][p].x), f1 = sigm_(acc2[1][p].y);
            float ga = tanh_(acc2[2][p].x), gb = tanh_(acc2[2][p].y);
            float o0 = sigm_(acc2[3][p].x), o1 = sigm_(acc2[3][p].y);
            float c0 = fmaf(f0, c[2 * p],     i0 * ga);
            float c1 = fmaf(f1, c[2 * p + 1], i1 * gb);
            c[2 * p] = c0; c[2 * p + 1] = c1;
            hval[2 * p]     = o0 * tanh_(c0);
            hval[2 * p + 1] = o1 * tanh_(c1);
        }
        {
            float ig = sigm_(accs[0]);
            float fg = sigm_(accs[1]);
            float gg = tanh_(accs[2]);
            float og = sigm_(accs[3]);
            float cn = fmaf(fg, c[4], ig * gg);
            c[4] = cn;
            hval[4] = og * tanh_(cn);
        }

        // publish own half: local smem + partner smem (DSMEM push) + arrive
        if (step < Lc - 1) {
            const int bofs = (step & 1) * HBUF + rg * RGSZ;
            float* hw = hsf + bofs;
            const uint32_t hwr = hs_r + (uint32_t)bofs * 4u;
#pragma unroll
            for (int r = 0; r < 5; r++) {
                const int idx = (((r >> 1) << 7) + col) * 2 + (r & 1);
                hw[idx] = hval[r];
                asm volatile("st.shared::cluster.f32 [%0], %1;"
                             :: "r"(hwr + (uint32_t)idx * 4u), "f"(hval[r])
                             : "memory");
            }
            BARRG(rg);   // own-half stores visible to sibling warp next step
            // release-arrive on partner's rg mbarrier (one per thread = 64)
            asm volatile(
                "mbarrier.arrive.release.cluster.shared::cluster.b64 _, [%0];"
                :: "r"(mb_r) : "memory");
        }

        // layer output (fire-and-forget)
#pragma unroll
        for (int r = 0; r < 5; r++)
            Xout[((size_t)(rbase + r) * Lc + tin) * 256 + dir * H + col] = hval[r];
    }

    // keep smem alive until partner is done with remote writes
    asm volatile("barrier.cluster.arrive.aligned;" ::: "memory");
    asm volatile("barrier.cluster.wait.aligned;" ::: "memory");
}

// ---------------------------------------------------------------------------
// Kernel 4: aggregation
// ---------------------------------------------------------------------------
__global__ __launch_bounds__(256) void agg_kernel(const float* __restrict__ X)
{
    int n = blockIdx.x, f = threadIdx.x;
    const float* base = X + (size_t)n * Lc * 256 + f;
    float s = 0.0f, m = -1e30f;
#pragma unroll 5
    for (int l = 0; l < Lc; l++) {
        float v = base[(size_t)l * 256];
        s += v; m = fmaxf(m, v);
    }
    g_agg[(size_t)n * 768 + f]       = s * (1.0f / Lc);
    g_agg[(size_t)n * 768 + 256 + f] = m;
    g_agg[(size_t)n * 768 + 512 + f] = (f < H) ? base[(Lc - 1) * 256] : base[0];
}

// ---------------------------------------------------------------------------
// Kernel 5: LayerNorm(512) + ReLU
// ---------------------------------------------------------------------------
__global__ __launch_bounds__(256) void ln_relu(
    const float* __restrict__ x, float* __restrict__ y,
    const float* __restrict__ gam, const float* __restrict__ bet)
{
    int row = blockIdx.x, tid = threadIdx.x;
    const float* xr = x + (size_t)row * 512;
    float v0 = xr[tid], v1 = xr[tid + 256];
    float s = v0 + v1, q = v0 * v0 + v1 * v1;
    __shared__ float ss[8], sq[8];
#pragma unroll
    for (int o = 16; o > 0; o >>= 1) {
        s += __shfl_down_sync(~0u, s, o);
        q += __shfl_down_sync(~0u, q, o);
    }
    int w = tid >> 5;
    if ((tid & 31) == 0) { ss[w] = s; sq[w] = q; }
    __syncthreads();
    if (tid == 0) {
        float S = 0.0f, Q = 0.0f;
        for (int i = 0; i < 8; i++) { S += ss[i]; Q += sq[i]; }
        ss[0] = S; sq[0] = Q;
    }
    __syncthreads();
    float mu  = ss[0] * (1.0f / 512.0f);
    float var = sq[0] * (1.0f / 512.0f) - mu * mu;
    float rs  = rsqrtf(var + 1e-5f);
    y[(size_t)row * 512 + tid]       = fmaxf((v0 - mu) * rs * gam[tid]       + bet[tid],       0.0f);
    y[(size_t)row * 512 + tid + 256] = fmaxf((v1 - mu) * rs * gam[tid + 256] + bet[tid + 256], 0.0f);
}

// ---------------------------------------------------------------------------
// Host orchestration
// ---------------------------------------------------------------------------
extern "C" void kernel_launch(void* const* d_in, const int* in_sizes, int n_in,
                              void* d_out, int out_size)
{
    const float* imu   = (const float*)d_in[0];
    const float* W_in  = (const float*)d_in[1];
    const float* b_in  = (const float*)d_in[2];
    const float* Wih[3] = {(const float*)d_in[3],  (const float*)d_in[7],  (const float*)d_in[11]};
    const float* Whh[3] = {(const float*)d_in[4],  (const float*)d_in[8],  (const float*)d_in[12]};
    const float* bih[3] = {(const float*)d_in[5],  (const float*)d_in[9],  (const float*)d_in[13]};
    const float* bhh[3] = {(const float*)d_in[6],  (const float*)d_in[10], (const float*)d_in[14]};
    const float* Wout1 = (const float*)d_in[15];
    const float* bout1 = (const float*)d_in[16];
    const float* ln_g  = (const float*)d_in[17];
    const float* ln_b  = (const float*)d_in[18];
    const float* Wout2 = (const float*)d_in[19];
    const float* bout2 = (const float*)d_in[20];
    float* out = (float*)d_out;

    float *pX0, *pXa, *pXb, *pxg, *pagg, *pt1, *pt2;
    cudaGetSymbolAddress((void**)&pX0,  g_X0);
    cudaGetSymbolAddress((void**)&pXa,  g_Xa);
    cudaGetSymbolAddress((void**)&pXb,  g_Xb);
    cudaGetSymbolAddress((void**)&pxg,  g_xg);
    cudaGetSymbolAddress((void**)&pagg, g_agg);
    cudaGetSymbolAddress((void**)&pt1,  g_t1);
    cudaGetSymbolAddress((void**)&pt2,  g_t2);

    cudaFuncSetAttribute(lstm_layer,
                         cudaFuncAttributeMaxDynamicSharedMemorySize, LSTM_SMEM);
    cudaFuncSetAttribute(tf32_gemm,
                         cudaFuncAttributeMaxDynamicSharedMemorySize, GEMM_SMEM);

    inproj_kernel<<<(NR * 64) / 256, 256>>>(imu, W_in, b_in);

    float* Xin  = pX0;
    int    Kin  = 64;
    float* Xout = pXa;
    for (int layer = 0; layer < 3; layer++) {
        tf32_gemm<<<dim3(8, NR / 128), 256, GEMM_SMEM>>>(
            Xin, Wih[layer], pxg, bih[layer], bhh[layer],
            NR, G4, Kin,
            (long long)Kin * G4, (long long)NR * G4, (long long)G4, 4, 1);
        lstm_layer<<<128, 512, LSTM_SMEM>>>(Whh[layer], pxg, Xout);
        Xin = Xout;
        Kin = 256;
        Xout = (Xin == pXa) ? pXb : pXa;
    }
    float* Xfinal = Xin;

    agg_kernel<<<NSEQ, 256>>>(Xfinal);
    tf32_gemm<<<dim3(4, NSEQ / 128), 256, GEMM_SMEM>>>(
        pagg, Wout1, pt1, bout1, nullptr, NSEQ, 512, 768, 0, 0, 0, 4, 0);
    ln_relu<<<NSEQ, 256>>>(pt1, pt2, ln_g, ln_b);
    tf32_gemm<<<dim3(2, NSEQ / 128), 256, GEMM_SMEM>>>(
        pt2, Wout2, out, bout2, nullptr, NSEQ, 256, 512, 0, 0, 0, 2, 0);
}

// round 13
// speedup vs baseline: 1.1001x; 1.0489x over previous
#include <cuda_runtime.h>
#include <math.h>
#include <stdint.h>

// Problem constants
constexpr int Lc    = 50;
constexpr int NSEQ  = 32 * 40;     // 1280 sequences
constexpr int NR    = NSEQ * Lc;   // 64000 (seq,time) rows
constexpr int H     = 128;
constexpr int G4    = 512;         // 4*H gates

// ---------------------------------------------------------------------------
// Device scratch
// ---------------------------------------------------------------------------
__device__ float g_X0[(size_t)NR * 64];
__device__ float g_Xa[(size_t)NR * 256];
__device__ float g_Xb[(size_t)NR * 256];
__device__ float g_xg[2][(size_t)NR * G4];   // t-major: [dir][t][seq][512]
__device__ float g_agg[(size_t)NSEQ * 768];
__device__ float g_t1[(size_t)NSEQ * 512];
__device__ float g_t2[(size_t)NSEQ * 512];

// ---------------------------------------------------------------------------
// helpers
// ---------------------------------------------------------------------------
__device__ __forceinline__ float2 ffma2(float2 a, float2 b, float2 c) {
    unsigned long long ud;
    asm("fma.rn.f32x2 %0, %1, %2, %3;"
        : "=l"(ud)
        : "l"(*(unsigned long long*)&a),
          "l"(*(unsigned long long*)&b),
          "l"(*(unsigned long long*)&c));
    float2 d; *(unsigned long long*)&d = ud; return d;
}
__device__ __forceinline__ float2 pack2(float lo, float hi) {
    float2 r; r.x = lo; r.y = hi; return r;
}
__device__ __forceinline__ float sigm_(float x) {
    return __fdividef(1.0f, 1.0f + __expf(-x));
}
__device__ __forceinline__ float tanh_(float x) {
    return __fdividef(2.0f, 1.0f + __expf(-2.0f * x)) - 1.0f;
}
__device__ __forceinline__ uint32_t f2tf(float x) {
    uint32_t r;
    asm("cvt.rna.tf32.f32 %0, %1;" : "=r"(r) : "f"(x));
    return r;
}
__device__ __forceinline__ void mma_tf32(float* d, const uint32_t* a,
                                         const uint32_t* b) {
    asm volatile(
        "mma.sync.aligned.m16n8k8.row.col.f32.tf32.tf32.f32 "
        "{%0,%1,%2,%3}, {%4,%5,%6,%7}, {%8,%9}, {%0,%1,%2,%3};\n"
        : "+f"(d[0]), "+f"(d[1]), "+f"(d[2]), "+f"(d[3])
        : "r"(a[0]), "r"(a[1]), "r"(a[2]), "r"(a[3]), "r"(b[0]), "r"(b[1]));
}
__device__ __forceinline__ uint32_t smem_u32(const void* p) {
    uint32_t a;
    asm("{ .reg .u64 t; cvta.to.shared.u64 t, %1; cvt.u32.u64 %0, t; }"
        : "=r"(a) : "l"(p));
    return a;
}

// ---------------------------------------------------------------------------
// Kernel 1: input projection
// ---------------------------------------------------------------------------
__global__ __launch_bounds__(256) void inproj_kernel(
    const float* __restrict__ imu, const float* __restrict__ Win,
    const float* __restrict__ bin)
{
    int idx = blockIdx.x * 256 + threadIdx.x;
    int row = idx >> 6;
    int jj  = idx & 63;
    int l   = row % Lc;
    const float* xr = imu + (size_t)row * 6;
    float t    = (float)l * (1.0f / 49.0f);
    float rate = 1.0f;
    float acc = bin[jj];
#pragma unroll
    for (int k = 0; k < 6; k++) acc = fmaf(xr[k], Win[k * 64 + jj], acc);
    acc = fmaf(t,    Win[6 * 64 + jj], acc);
    acc = fmaf(rate, Win[7 * 64 + jj], acc);
    g_X0[(size_t)row * 64 + jj] = fmaxf(acc, 0.0f);
}

// ---------------------------------------------------------------------------
// Kernel 2: tf32 tensor-core GEMM + bias.
// Block tile 128x256, BK=16, 8 warps (2 row x 4 col) of 64x64 warp tiles.
// m16n8k8 tf32 HMMA; double-buffered smem; permute: t-major output rows.
// Fragment reuse: 0.125 B/MAC through smem (vs 0.19 in the 128x128 version).
// ---------------------------------------------------------------------------
constexpr int APITCH = 132;                 // floats per (ks,c) A row (128 q + pad)
constexpr int BPITCH = 516;                 // floats per (ks,kp) B row (256*2 + pad)
constexpr int ASZ = 2 * 8 * APITCH;         // floats per A buffer (2 ks groups)
constexpr int BSZ = 2 * 4 * BPITCH;         // floats per B buffer
constexpr int GEMM_SMEM = (2 * ASZ + 2 * BSZ) * 4;   // 49,920 bytes

__device__ __forceinline__ int asI(int buf, int ks, int c, int q) {
    return ((buf * 2 + ks) * 8 + c) * APITCH + q;
}
__device__ __forceinline__ int bsI(int buf, int ks, int kp, int q) {
    return ((buf * 2 + ks) * 4 + kp) * BPITCH + q;
}

__global__ __launch_bounds__(256) void tf32_gemm(
    const float* __restrict__ A, const float* __restrict__ B,
    float* __restrict__ C,
    const float* __restrict__ bias1, const float* __restrict__ bias2,
    int M, int N, int K,
    long long sB, long long sC, long long sBias, int nbx, int permute)
{
    extern __shared__ uint32_t sm[];
    uint32_t* As = sm;               // [2][2][8][APITCH]
    uint32_t* Bs = sm + 2 * ASZ;     // [2][2][4][BPITCH]

    const int dir = blockIdx.x / nbx;
    const int nb  = blockIdx.x % nbx;
    const int mb  = blockIdx.y;
    B += (size_t)dir * sB;
    C += (size_t)dir * sC;
    const float* b1 = bias1 + (size_t)dir * sBias;
    const float* b2 = bias2 ? bias2 + (size_t)dir * sBias : nullptr;
    const bool hasB2 = (b2 != nullptr);

    const int tid  = threadIdx.x;
    const int warp = tid >> 5, lane = tid & 31;
    const int wR = warp >> 2, wC = warp & 3;     // 2 x 4 warps, 64x64 each
    const int g  = lane >> 2, tig = lane & 3;

    const float* Ab = A + (size_t)(mb * 128) * K;
    const float* Bb = B + nb * 256;

    // A loader: row = tid>>1 (0..127), ks = tid&1, two float4 (c0 = 0, 4)
    const int aRow = tid >> 1;
    const int aks  = tid & 1;
    const int aQ   = ((aRow >> 4) << 4) + ((aRow & 7) << 1) + ((aRow >> 3) & 1);
    // B loader: k = tid>>4 (0..15), four float4 across 256 cols
    const int bk   = tid >> 4;
    const int bks  = bk >> 3, br8 = bk & 7;
    const int bkp  = br8 & 3, bhalf = br8 >> 2;
    const int bn0  = (tid & 15) * 4;

    float acc[4][8][4];
#pragma unroll
    for (int mt = 0; mt < 4; mt++)
#pragma unroll
        for (int nt = 0; nt < 8; nt++)
#pragma unroll
            for (int q = 0; q < 4; q++) acc[mt][nt][q] = 0.0f;

    const int niter = K / 16;

    // prologue: k-tile 0 -> buffer 0
    {
#pragma unroll
        for (int j = 0; j < 2; j++) {
            float4 v = *(const float4*)(Ab + (size_t)aRow * K + aks * 8 + j * 4);
            uint32_t* d = &As[asI(0, aks, j * 4, aQ)];
            d[0] = f2tf(v.x); d[APITCH] = f2tf(v.y);
            d[2 * APITCH] = f2tf(v.z); d[3 * APITCH] = f2tf(v.w);
        }
#pragma unroll
        for (int i = 0; i < 4; i++) {
            int n0 = bn0 + i * 64;
            float4 v = *(const float4*)(Bb + (size_t)bk * N + n0);
            uint32_t* d = &Bs[bsI(0, bks, bkp, n0 * 2 + bhalf)];
            d[0] = f2tf(v.x); d[2] = f2tf(v.y);
            d[4] = f2tf(v.z); d[6] = f2tf(v.w);
        }
    }
    __syncthreads();

    for (int it = 0; it < niter; it++) {
        const int cur = it & 1, nxt = cur ^ 1;
        const bool more = (it + 1 < niter);
        float4 av[2], bv[4];
        if (more) {
            int k0 = (it + 1) * 16;
#pragma unroll
            for (int j = 0; j < 2; j++)
                av[j] = *(const float4*)(Ab + (size_t)aRow * K + k0 + aks * 8 + j * 4);
#pragma unroll
            for (int i = 0; i < 4; i++)
                bv[i] = *(const float4*)(Bb + (size_t)(k0 + bk) * N + bn0 + i * 64);
        }

#pragma unroll
        for (int ks = 0; ks < 2; ks++) {
            uint32_t af[4][4];
#pragma unroll
            for (int mt = 0; mt < 4; mt++) {
                int q = ((wR * 4 + mt) << 4) + (g << 1);
                uint2 u0 = *(const uint2*)&As[asI(cur, ks, tig, q)];
                uint2 u1 = *(const uint2*)&As[asI(cur, ks, tig + 4, q)];
                af[mt][0] = u0.x; af[mt][1] = u0.y;
                af[mt][2] = u1.x; af[mt][3] = u1.y;
            }
            uint32_t bf[8][2];
#pragma unroll
            for (int nt = 0; nt < 8; nt++) {
                int n = wC * 64 + nt * 8 + g;
                uint2 u = *(const uint2*)&Bs[bsI(cur, ks, tig, n * 2)];
                bf[nt][0] = u.x; bf[nt][1] = u.y;
            }
#pragma unroll
            for (int mt = 0; mt < 4; mt++)
#pragma unroll
                for (int nt = 0; nt < 8; nt++)
                    mma_tf32(acc[mt][nt], af[mt], bf[nt]);
        }

        if (more) {
#pragma unroll
            for (int j = 0; j < 2; j++) {
                uint32_t* d = &As[asI(nxt, aks, j * 4, aQ)];
                d[0] = f2tf(av[j].x); d[APITCH] = f2tf(av[j].y);
                d[2 * APITCH] = f2tf(av[j].z); d[3 * APITCH] = f2tf(av[j].w);
            }
#pragma unroll
            for (int i = 0; i < 4; i++) {
                int n0 = bn0 + i * 64;
                uint32_t* d = &Bs[bsI(nxt, bks, bkp, n0 * 2 + bhalf)];
                d[0] = f2tf(bv[i].x); d[2] = f2tf(bv[i].y);
                d[4] = f2tf(bv[i].z); d[6] = f2tf(bv[i].w);
            }
        }
        __syncthreads();
    }

    // epilogue
#pragma unroll
    for (int mt = 0; mt < 4; mt++) {
        int rowa = mb * 128 + wR * 64 + mt * 16 + g;
        int rowb = rowa + 8;
        size_t ra = permute ? ((size_t)(rowa % Lc) * NSEQ + rowa / Lc) : (size_t)rowa;
        size_t rb = permute ? ((size_t)(rowb % Lc) * NSEQ + rowb / Lc) : (size_t)rowb;
#pragma unroll
        for (int nt = 0; nt < 8; nt++) {
            int colg = nb * 256 + wC * 64 + nt * 8 + 2 * tig;
            float bx = b1[colg], by = b1[colg + 1];
            if (hasB2) { bx += b2[colg]; by += b2[colg + 1]; }
            float2 v0 = pack2(acc[mt][nt][0] + bx, acc[mt][nt][1] + by);
            float2 v1 = pack2(acc[mt][nt][2] + bx, acc[mt][nt][3] + by);
            *(float2*)(C + ra * N + colg) = v0;
            *(float2*)(C + rb * N + colg) = v1;
        }
    }
}

// ---------------------------------------------------------------------------
// Kernel 3: PERSISTENT BiLSTM layer — DSMEM push exchange (round-12 version).
// ---------------------------------------------------------------------------
#define BARRG(rgid) asm volatile("bar.sync %0, 64;" :: "r"(rgid) : "memory")

constexpr int RGSZ = 3 * 128 * 2;              // floats per rg slice
constexpr int HBUF = 8 * RGSZ;                 // floats per h buffer
constexpr int LSTM_SMEM = 128 * 64 * 16        // ws
                        + 2 * HBUF * 4         // double-buffered h
                        + 8 * 8;               // 8 mbarriers

__global__ __launch_bounds__(512) __cluster_dims__(2, 1, 1)
void lstm_layer(const float* __restrict__ Whh,
                const float* __restrict__ xgb,   // t-major [dir][t][seq][512]
                float* __restrict__ Xout)
{
    extern __shared__ float smem[];
    float4* ws  = (float4*)smem;                 // [128][64] gate quads
    float*  hsf = smem + 128 * 64 * 4;           // 2 x HBUF
    unsigned long long* mbar =
        (unsigned long long*)(hsf + 2 * HBUF);   // [8] per-rg mbarriers

    const int bx   = blockIdx.x;
    const int dir  = bx >> 6;
    const int jt   = bx & 1;                     // cluster rank
    const int rgI  = (bx >> 1) & 31;
    const int row0 = rgI * 40;
    const int tid  = threadIdx.x;
    const int warp = tid >> 5, lane = tid & 31;
    const int rg   = warp >> 1, jh = warp & 1;
    const int jcol = (jh << 5) + lane;           // 0..63
    const int col  = (jt << 6) + jcol;           // 0..127
    const int rbase = row0 + rg * 5;

    const float* W   = Whh + (size_t)dir * (H * G4);
    const float* xgd = xgb + (size_t)dir * NR * G4;

    if (tid < 8) {
        uint32_t mb = smem_u32(&mbar[tid]);
        asm volatile("mbarrier.init.shared.b64 [%0], %1;"
                     :: "r"(mb), "r"(64) : "memory");
    }

    for (int idx = tid; idx < 128 * 64; idx += 512) {
        int k = idx >> 6, j = idx & 63;
        const float* wk = W + (size_t)k * G4 + (jt << 6) + j;
        ws[idx] = make_float4(wk[0], wk[128], wk[256], wk[384]);
    }
    __syncthreads();
    asm volatile("barrier.cluster.arrive.aligned;" ::: "memory");
    asm volatile("barrier.cluster.wait.aligned;" ::: "memory");

    const uint32_t mb_l = smem_u32(&mbar[rg]);
    uint32_t mb_r;
    asm("mapa.shared::cluster.u32 %0, %1, %2;"
        : "=r"(mb_r) : "r"(mb_l), "r"(jt ^ 1));
    const uint32_t hs_l = smem_u32(hsf);
    uint32_t hs_r;
    asm("mapa.shared::cluster.u32 %0, %1, %2;"
        : "=r"(hs_r) : "r"(hs_l), "r"(jt ^ 1));

    float c[5];
#pragma unroll
    for (int r = 0; r < 5; r++) c[r] = 0.0f;

    for (int step = 0; step < Lc; step++) {
        const int tin = dir ? (Lc - 1 - step) : step;

        float2 acc2[4][2];
        float  accs[4];
        const float* xp = xgd + ((size_t)tin * NSEQ + rbase) * G4 + col;
#pragma unroll
        for (int p = 0; p < 2; p++) {
            const float* xa = xp + (size_t)(2 * p) * G4;
            const float* xb = xa + G4;
#pragma unroll
            for (int gi = 0; gi < 4; gi++)
                acc2[gi][p] = pack2(xa[gi * 128], xb[gi * 128]);
        }
        {
            const float* xa = xp + (size_t)4 * G4;
#pragma unroll
            for (int gi = 0; gi < 4; gi++) accs[gi] = xa[gi * 128];
        }

        if (step > 0) {
            {
                const uint32_t parity = (uint32_t)((step - 1) & 1);
                uint32_t done;
                do {
                    asm volatile(
                        "{\n\t.reg .pred p;\n\t"
                        "mbarrier.try_wait.parity.acquire.cluster.shared::cta.b64 "
                        "p, [%1], %2;\n\t"
                        "selp.b32 %0, 1, 0, p;\n\t}"
                        : "=r"(done) : "r"(mb_l), "r"(parity) : "memory");
                } while (!done);
            }

            const float*  hrow  = hsf + ((step + 1) & 1) * HBUF + rg * RGSZ;
            const float2* hrow2 = (const float2*)hrow;
#pragma unroll 8
            for (int k = 0; k < 128; k++) {
                float4 w4 = ws[(k << 6) + jcol];
                float2 ha = hrow2[k];
                float2 hb = hrow2[128 + k];
                float  hc = hrow[(256 + k) * 2];
                float2 w0 = pack2(w4.x, w4.x);
                float2 w1 = pack2(w4.y, w4.y);
                float2 w2 = pack2(w4.z, w4.z);
                float2 w3 = pack2(w4.w, w4.w);
                acc2[0][0] = ffma2(ha, w0, acc2[0][0]);
                acc2[1][0] = ffma2(ha, w1, acc2[1][0]);
                acc2[2][0] = ffma2(ha, w2, acc2[2][0]);
                acc2[3][0] = ffma2(ha, w3, acc2[3][0]);
                acc2[0][1] = ffma2(hb, w0, acc2[0][1]);
                acc2[1][1] = ffma2(hb, w1, acc2[1][1]);
                acc2[2][1] = ffma2(hb, w2, acc2[2][1]);
                acc2[3][1] = ffma2(hb, w3, acc2[3][1]);
                accs[0] = fmaf(hc, w4.x, accs[0]);
                accs[1] = fmaf(hc, w4.y, accs[1]);
                accs[2] = fmaf(hc, w4.z, accs[2]);
                accs[3] = fmaf(hc, w4.w, accs[3]);
            }
        }

        float hval[5];
#pragma unroll
        for (int p = 0; p < 2; p++) {
            float i0 = sigm_(acc2[0][p].x), i1 = sigm_(acc2[0][p].y);
            float f0 = sigm_(acc2[1][p].x), f1 = sigm_(acc2[1][p].y);
            float ga = tanh_(acc2[2][p].x), gb = tanh_(acc2[2][p].y);
            float o0 = sigm_(acc2[3][p].x), o1 = sigm_(acc2[3][p].y);
            float c0 = fmaf(f0, c[2 * p],     i0 * ga);
            float c1 = fmaf(f1, c[2 * p + 1], i1 * gb);
            c[2 * p] = c0; c[2 * p + 1] = c1;
            hval[2 * p]     = o0 * tanh_(c0);
            hval[2 * p + 1] = o1 * tanh_(c1);
        }
        {
            float ig = sigm_(accs[0]);
            float fg = sigm_(accs[1]);
            float gg = tanh_(accs[2]);
            float og = sigm_(accs[3]);
            float cn = fmaf(fg, c[4], ig * gg);
            c[4] = cn;
            hval[4] = og * tanh_(cn);
        }

        if (step < Lc - 1) {
            const int bofs = (step & 1) * HBUF + rg * RGSZ;
            float* hw = hsf + bofs;
            const uint32_t hwr = hs_r + (uint32_t)bofs * 4u;
#pragma unroll
            for (int r = 0; r < 5; r++) {
                const int idx = (((r >> 1) << 7) + col) * 2 + (r & 1);
                hw[idx] = hval[r];
                asm volatile("st.shared::cluster.f32 [%0], %1;"
                             :: "r"(hwr + (uint32_t)idx * 4u), "f"(hval[r])
                             : "memory");
            }
            BARRG(rg);
            asm volatile(
                "mbarrier.arrive.release.cluster.shared::cluster.b64 _, [%0];"
                :: "r"(mb_r) : "memory");
        }

#pragma unroll
        for (int r = 0; r < 5; r++)
            Xout[((size_t)(rbase + r) * Lc + tin) * 256 + dir * H + col] = hval[r];
    }

    asm volatile("barrier.cluster.arrive.aligned;" ::: "memory");
    asm volatile("barrier.cluster.wait.aligned;" ::: "memory");
}

// ---------------------------------------------------------------------------
// Kernel 4: aggregation
// ---------------------------------------------------------------------------
__global__ __launch_bounds__(256) void agg_kernel(const float* __restrict__ X)
{
    int n = blockIdx.x, f = threadIdx.x;
    const float* base = X + (size_t)n * Lc * 256 + f;
    float s = 0.0f, m = -1e30f;
#pragma unroll 5
    for (int l = 0; l < Lc; l++) {
        float v = base[(size_t)l * 256];
        s += v; m = fmaxf(m, v);
    }
    g_agg[(size_t)n * 768 + f]       = s * (1.0f / Lc);
    g_agg[(size_t)n * 768 + 256 + f] = m;
    g_agg[(size_t)n * 768 + 512 + f] = (f < H) ? base[(Lc - 1) * 256] : base[0];
}

// ---------------------------------------------------------------------------
// Kernel 5: LayerNorm(512) + ReLU
// ---------------------------------------------------------------------------
__global__ __launch_bounds__(256) void ln_relu(
    const float* __restrict__ x, float* __restrict__ y,
    const float* __restrict__ gam, const float* __restrict__ bet)
{
    int row = blockIdx.x, tid = threadIdx.x;
    const float* xr = x + (size_t)row * 512;
    float v0 = xr[tid], v1 = xr[tid + 256];
    float s = v0 + v1, q = v0 * v0 + v1 * v1;
    __shared__ float ss[8], sq[8];
#pragma unroll
    for (int o = 16; o > 0; o >>= 1) {
        s += __shfl_down_sync(~0u, s, o);
        q += __shfl_down_sync(~0u, q, o);
    }
    int w = tid >> 5;
    if ((tid & 31) == 0) { ss[w] = s; sq[w] = q; }
    __syncthreads();
    if (tid == 0) {
        float S = 0.0f, Q = 0.0f;
        for (int i = 0; i < 8; i++) { S += ss[i]; Q += sq[i]; }
        ss[0] = S; sq[0] = Q;
    }
    __syncthreads();
    float mu  = ss[0] * (1.0f / 512.0f);
    float var = sq[0] * (1.0f / 512.0f) - mu * mu;
    float rs  = rsqrtf(var + 1e-5f);
    y[(size_t)row * 512 + tid]       = fmaxf((v0 - mu) * rs * gam[tid]       + bet[tid],       0.0f);
    y[(size_t)row * 512 + tid + 256] = fmaxf((v1 - mu) * rs * gam[tid + 256] + bet[tid + 256], 0.0f);
}

// ---------------------------------------------------------------------------
// Host orchestration
// ---------------------------------------------------------------------------
extern "C" void kernel_launch(void* const* d_in, const int* in_sizes, int n_in,
                              void* d_out, int out_size)
{
    const float* imu   = (const float*)d_in[0];
    const float* W_in  = (const float*)d_in[1];
    const float* b_in  = (const float*)d_in[2];
    const float* Wih[3] = {(const float*)d_in[3],  (const float*)d_in[7],  (const float*)d_in[11]};
    const float* Whh[3] = {(const float*)d_in[4],  (const float*)d_in[8],  (const float*)d_in[12]};
    const float* bih[3] = {(const float*)d_in[5],  (const float*)d_in[9],  (const float*)d_in[13]};
    const float* bhh[3] = {(const float*)d_in[6],  (const float*)d_in[10], (const float*)d_in[14]};
    const float* Wout1 = (const float*)d_in[15];
    const float* bout1 = (const float*)d_in[16];
    const float* ln_g  = (const float*)d_in[17];
    const float* ln_b  = (const float*)d_in[18];
    const float* Wout2 = (const float*)d_in[19];
    const float* bout2 = (const float*)d_in[20];
    float* out = (float*)d_out;

    float *pX0, *pXa, *pXb, *pxg, *pagg, *pt1, *pt2;
    cudaGetSymbolAddress((void**)&pX0,  g_X0);
    cudaGetSymbolAddress((void**)&pXa,  g_Xa);
    cudaGetSymbolAddress((void**)&pXb,  g_Xb);
    cudaGetSymbolAddress((void**)&pxg,  g_xg);
    cudaGetSymbolAddress((void**)&pagg, g_agg);
    cudaGetSymbolAddress((void**)&pt1,  g_t1);
    cudaGetSymbolAddress((void**)&pt2,  g_t2);

    cudaFuncSetAttribute(lstm_layer,
                         cudaFuncAttributeMaxDynamicSharedMemorySize, LSTM_SMEM);
    cudaFuncSetAttribute(tf32_gemm,
                         cudaFuncAttributeMaxDynamicSharedMemorySize, GEMM_SMEM);

    inproj_kernel<<<(NR * 64) / 256, 256>>>(imu, W_in, b_in);

    float* Xin  = pX0;
    int    Kin  = 64;
    float* Xout = pXa;
    for (int layer = 0; layer < 3; layer++) {
        // xg = Xin @ Wih + (bih+bhh); N=512 per dir -> nbx=2; both dirs in grid.x
        tf32_gemm<<<dim3(4, NR / 128), 256, GEMM_SMEM>>>(
            Xin, Wih[layer], pxg, bih[layer], bhh[layer],
            NR, G4, Kin,
            (long long)Kin * G4, (long long)NR * G4, (long long)G4, 2, 1);
        lstm_layer<<<128, 512, LSTM_SMEM>>>(Whh[layer], pxg, Xout);
        Xin = Xout;
        Kin = 256;
        Xout = (Xin == pXa) ? pXb : pXa;
    }
    float* Xfinal = Xin;

    agg_kernel<<<NSEQ, 256>>>(Xfinal);
    tf32_gemm<<<dim3(2, NSEQ / 128), 256, GEMM_SMEM>>>(
        pagg, Wout1, pt1, bout1, nullptr, NSEQ, 512, 768, 0, 0, 0, 2, 0);
    ln_relu<<<NSEQ, 256>>>(pt1, pt2, ln_g, ln_b);
    tf32_gemm<<<dim3(1, NSEQ / 128), 256, GEMM_SMEM>>>(
        pt2, Wout2, out, bout2, nullptr, NSEQ, 256, 512, 0, 0, 0, 1, 0);
}